// round 10
// baseline (speedup 1.0000x reference)
#include <cuda_runtime.h>
#include <cuda_bf16.h>
#include <cuda_fp16.h>
#include <math.h>
#include <stdint.h>

// Problem constants (fixed by setup_inputs)
#define T_MAX 4096
#define D_MODEL 1280
#define NHEAD 16
#define HD 80
#define E3 (3 * D_MODEL)   // 3840
#define WIN 64
#define KDIM 1280

// ---------------------------------------------------------------------------
// Scratch (device globals; no allocations allowed)
// ---------------------------------------------------------------------------
__device__ float g_qkv[T_MAX * E3];

__device__ __half g_xh[T_MAX * D_MODEL];      // x split hi/lo (fp16)
__device__ __half g_xl[T_MAX * D_MODEL];
__device__ __half g_wq[E3 * D_MODEL];         // Wqkv^T [N,K] fp16
__device__ __half g_wo[D_MODEL * D_MODEL];    // Wo^T [N,K] fp16
__device__ __half g_ah[T_MAX * D_MODEL];      // attn out split hi/lo (fp16)
__device__ __half g_al[T_MAX * D_MODEL];

// ---------------------------------------------------------------------------
// Low-level helpers (baseline PTX, safe for compute_100)
// ---------------------------------------------------------------------------
__device__ __forceinline__ uint32_t smem_u32(const void* p) {
    uint32_t a;
    asm("{ .reg .u64 t; cvta.to.shared.u64 t, %1; cvt.u32.u64 %0, t; }"
        : "=r"(a) : "l"(p));
    return a;
}

__device__ __forceinline__ void cp_async16(uint32_t dst, const void* src) {
    asm volatile("cp.async.cg.shared.global [%0], [%1], 16;" :: "r"(dst), "l"(src));
}

__device__ __forceinline__ void ldm_x4(uint32_t* r, uint32_t addr) {
    asm volatile("ldmatrix.sync.aligned.m8n8.x4.shared.b16 {%0,%1,%2,%3}, [%4];"
                 : "=r"(r[0]), "=r"(r[1]), "=r"(r[2]), "=r"(r[3]) : "r"(addr));
}

__device__ __forceinline__ void mma_fp16(float* d, const uint32_t* a, const uint32_t* b) {
    asm volatile(
        "mma.sync.aligned.m16n8k16.row.col.f32.f16.f16.f32 "
        "{%0,%1,%2,%3}, {%4,%5,%6,%7}, {%8,%9}, {%0,%1,%2,%3};"
        : "+f"(d[0]), "+f"(d[1]), "+f"(d[2]), "+f"(d[3])
        : "r"(a[0]), "r"(a[1]), "r"(a[2]), "r"(a[3]), "r"(b[0]), "r"(b[1]));
}

// ---------------------------------------------------------------------------
// GEMM: C[M,N] = (Ah+Al)[M,K] @ B[N,K]^T + bias[N]  (fp32 accum, fp16 ops)
// Templated on BM (128 for QKV, 64 for Wo to fix wave quantization).
// BN=128, BK=32, 4-stage cp.async pipeline, 1 sync/chunk, XOR-swizzled rows.
// ---------------------------------------------------------------------------
#define GBN 128
#define GBK 32
#define NSTAGE 4

__device__ __forceinline__ uint32_t sw_off(int row, int ch) {
    return (uint32_t)(row * 64) + ((uint32_t)(ch ^ ((row >> 1) & 3)) << 4);
}

template <int BM>
__global__ void __launch_bounds__(256, 2)
gemm_fp16x2(int M, int N, int K,
            const __half* __restrict__ Ah, const __half* __restrict__ Al,
            const __half* __restrict__ B,
            const float* __restrict__ bias, float* __restrict__ C)
{
    constexpr int WM     = BM / 2;          // warp M extent (64 or 32)
    constexpr int MI     = WM / 16;         // m16 frags per warp (4 or 2)
    constexpr int TILE_A = BM * 64;         // bytes per A sub-tile
    constexpr int TILE_BB = 128 * 64;       // bytes for B sub-tile
    constexpr int STAGE  = 2 * TILE_A + TILE_BB;
    constexpr int JA     = (BM * 4) / 256;  // loader iters per A tile (2 or 1)

    extern __shared__ __align__(128) char dsm[];
    const uint32_t sbase = smem_u32(dsm);

    const int tid  = threadIdx.x;
    const int wid  = tid >> 5;
    const int lane = tid & 31;
    const int warp_m = wid >> 2;       // 0..1
    const int warp_n = wid & 3;        // 0..3
    const int m0 = blockIdx.y * BM;
    const int n0 = blockIdx.x * GBN;

    const int NC = K / GBK;            // 40

    auto load_stage = [&](int cidx) {
        const uint32_t sb = sbase + (uint32_t)(cidx % NSTAGE) * STAGE;
        const int k0 = cidx * GBK;
        // A tiles (Ah, Al): BM rows x 4 chunks
        {
            const __half* pa[2] = { Ah + (size_t)m0 * K + k0,
                                    Al + (size_t)m0 * K + k0 };
            #pragma unroll
            for (int t = 0; t < 2; ++t)
                #pragma unroll
                for (int j = 0; j < JA; ++j) {
                    int e   = tid + j * 256;
                    int row = e >> 2;
                    int ch  = e & 3;
                    cp_async16(sb + (uint32_t)t * TILE_A + sw_off(row, ch),
                               pa[t] + (size_t)row * K + ch * 8);
                }
        }
        // B tile: 128 rows x 4 chunks
        {
            const __half* pb = B + (size_t)n0 * K + k0;
            #pragma unroll
            for (int j = 0; j < 2; ++j) {
                int e   = tid + j * 256;
                int row = e >> 2;
                int ch  = e & 3;
                cp_async16(sb + (uint32_t)(2 * TILE_A) + sw_off(row, ch),
                           pb + (size_t)row * K + ch * 8);
            }
        }
        asm volatile("cp.async.commit_group;");
    };

    float acc[MI][4][4];
    #pragma unroll
    for (int i = 0; i < MI; ++i)
        #pragma unroll
        for (int j = 0; j < 4; ++j)
            #pragma unroll
            for (int q = 0; q < 4; ++q) acc[i][j][q] = 0.f;

    load_stage(0);
    load_stage(1);
    load_stage(2);

    const int a_row = lane & 15;
    const int a_kch = (lane >> 4);
    const int b_row = (lane & 7) + ((lane >> 4) << 3);
    const int b_kch = ((lane >> 3) & 1);

    for (int c = 0; c < NC; ++c) {
        if (c + 2 < NC) {
            asm volatile("cp.async.wait_group 2;");
        } else if (c + 1 < NC) {
            asm volatile("cp.async.wait_group 1;");
        } else {
            asm volatile("cp.async.wait_group 0;");
        }
        __syncthreads();
        if (c + 3 < NC) load_stage(c + 3);

        const uint32_t sb = sbase + (uint32_t)(c % NSTAGE) * STAGE;

        #pragma unroll
        for (int kk = 0; kk < 2; ++kk) {
            const int kc = kk * 2;
            uint32_t aH[MI][4], bF[2][4];
            #pragma unroll
            for (int ma = 0; ma < MI; ++ma) {
                int row = warp_m * WM + ma * 16 + a_row;
                ldm_x4(aH[ma], sb + 0 * TILE_A + sw_off(row, kc + a_kch));
            }
            #pragma unroll
            for (int np = 0; np < 2; ++np) {
                int row = warp_n * 32 + np * 16 + b_row;
                ldm_x4(bF[np], sb + (uint32_t)(2 * TILE_A) + sw_off(row, kc + b_kch));
            }
            #pragma unroll
            for (int ma = 0; ma < MI; ++ma)
                #pragma unroll
                for (int nb = 0; nb < 4; ++nb)
                    mma_fp16(acc[ma][nb], aH[ma], &bF[nb >> 1][(nb & 1) * 2]);
            uint32_t aL[MI][4];
            #pragma unroll
            for (int ma = 0; ma < MI; ++ma) {
                int row = warp_m * WM + ma * 16 + a_row;
                ldm_x4(aL[ma], sb + 1 * TILE_A + sw_off(row, kc + a_kch));
            }
            #pragma unroll
            for (int ma = 0; ma < MI; ++ma)
                #pragma unroll
                for (int nb = 0; nb < 4; ++nb)
                    mma_fp16(acc[ma][nb], aL[ma], &bF[nb >> 1][(nb & 1) * 2]);
        }
    }

    const int er = lane >> 2;
    const int ec = (lane & 3) * 2;
    #pragma unroll
    for (int ma = 0; ma < MI; ++ma) {
        int gr = m0 + warp_m * WM + ma * 16 + er;
        #pragma unroll
        for (int nb = 0; nb < 4; ++nb) {
            int gc = n0 + warp_n * 32 + nb * 8 + ec;
            float b0 = __ldg(&bias[gc]);
            float b1 = __ldg(&bias[gc + 1]);
            float2 v0 = make_float2(acc[ma][nb][0] + b0, acc[ma][nb][1] + b1);
            float2 v1 = make_float2(acc[ma][nb][2] + b0, acc[ma][nb][3] + b1);
            *(float2*)&C[(size_t)gr * N + gc] = v0;
            *(float2*)&C[(size_t)(gr + 8) * N + gc] = v1;
        }
    }
}

// ---------------------------------------------------------------------------
// Split fp32 -> fp16 hi/lo
// ---------------------------------------------------------------------------
__global__ void split_f16_kernel(const float* __restrict__ x,
                                 __half* __restrict__ h,
                                 __half* __restrict__ l, int n)
{
    int i = blockIdx.x * blockDim.x + threadIdx.x;
    if (i < n) {
        float v = x[i];
        __half hi = __float2half_rn(v);
        h[i] = hi;
        l[i] = __float2half_rn(v - __half2float(hi));
    }
}

// ---------------------------------------------------------------------------
// Transpose + convert: W[K,N] fp32 -> Wt [N,K] fp16
// ---------------------------------------------------------------------------
__global__ void transpose_f16_kernel(const float* __restrict__ W,
                                     __half* __restrict__ t,
                                     int Kd, int Nd)
{
    __shared__ float tile[32][33];
    int kb = blockIdx.y * 32, nb = blockIdx.x * 32;
    int tx = threadIdx.x, ty = threadIdx.y;    // 32 x 8
    #pragma unroll
    for (int i = 0; i < 32; i += 8)
        tile[ty + i][tx] = W[(size_t)(kb + ty + i) * Nd + nb + tx];
    __syncthreads();
    #pragma unroll
    for (int i = 0; i < 32; i += 8)
        t[(size_t)(nb + ty + i) * Kd + kb + tx] = __float2half_rn(tile[tx][ty + i]);
}

// ---------------------------------------------------------------------------
// Fused RoPE + windowed causal attention + fp16 split epilogue.
// 256 threads per (segment, head). Causality-pruned S phase, half2 V tile.
// ---------------------------------------------------------------------------
#define QKS 81
#define SST 65
#define VST 40   // half2 stride for V tile

__global__ void __launch_bounds__(256, 2)
attn_fused_kernel(const int* __restrict__ cu, const float* __restrict__ rope,
                  int T,
                  __half* __restrict__ ah, __half* __restrict__ al)
{
    extern __shared__ float sm[];
    float*   Qs  = sm;                        // [64][81]
    float*   Ks  = Qs + WIN * QKS;            // [64][81]
    __half2* Vs2 = (__half2*)(Ks + WIN * QKS);// [64][40] half2
    float*   S   = (float*)(Vs2 + WIN * VST); // [64][65]

    const int seg = blockIdx.x;
    const int h   = blockIdx.y;
    const int st  = cu[seg];
    int L = cu[seg + 1] - st;
    if (L > WIN) L = WIN;
    const int tid = threadIdx.x;
    const float scale = 0.11180339887498948f;   // 1/sqrt(80)

    // ---- load + RoPE ------------------------------------------------------
    for (int e = tid; e < WIN * 40; e += 256) {
        int r = e / 40, j = e % 40;
        float q0 = 0.f, q1 = 0.f, k0 = 0.f, k1 = 0.f;
        if (r < L) {
            size_t base = (size_t)(st + r) * E3 + (size_t)h * HD;
            float ang = rope[(st + r) * 40 + j];
            float c = cosf(ang), s = sinf(ang);
            float qr = g_qkv[base + j],           qi = g_qkv[base + 40 + j];
            float kr = g_qkv[base + D_MODEL + j], ki = g_qkv[base + D_MODEL + 40 + j];
            q0 = qr * c - qi * s;  q1 = qr * s + qi * c;
            k0 = kr * c - ki * s;  k1 = kr * s + ki * c;
        }
        Qs[r * QKS + j]      = q0;
        Qs[r * QKS + 40 + j] = q1;
        Ks[r * QKS + j]      = k0;
        Ks[r * QKS + 40 + j] = k1;
    }
    // V -> half2 tile (d pairs contiguous)
    for (int e = tid; e < WIN * VST; e += 256) {
        int r = e / VST, dp = e % VST;
        float2 v = make_float2(0.f, 0.f);
        if (r < L) {
            const float* p = &g_qkv[(size_t)(st + r) * E3 + (size_t)h * HD
                                    + 2 * D_MODEL + 2 * dp];
            v.x = p[0]; v.y = p[1];
        }
        Vs2[r * VST + dp] = __floats2half2_rn(v.x, v.y);
    }
    __syncthreads();

    // ---- S = Q K^T * scale  (2-row x NJ-col tile, causality-pruned) -------
    {
        const int rg = tid >> 3;           // rows 2rg, 2rg+1
        const int cg = tid & 7;            // cols cg + 8*j
        const int cmax = 2 * rg + 1;
        const int NJ = (cmax >= cg) ? (((cmax - cg) >> 3) + 1) : 0;
        float accS[2][8];
        #pragma unroll
        for (int i = 0; i < 2; ++i)
            #pragma unroll
            for (int j = 0; j < 8; ++j) accS[i][j] = 0.f;
        for (int d = 0; d < HD; ++d) {
            float qv0 = Qs[(rg * 2) * QKS + d];
            float qv1 = Qs[(rg * 2 + 1) * QKS + d];
            for (int j = 0; j < NJ; ++j) {
                float kvj = Ks[(cg + 8 * j) * QKS + d];
                accS[0][j] += qv0 * kvj;
                accS[1][j] += qv1 * kvj;
            }
        }
        for (int j = 0; j < NJ; ++j) {
            S[(rg * 2) * SST + cg + 8 * j]     = accS[0][j] * scale;
            S[(rg * 2 + 1) * SST + cg + 8 * j] = accS[1][j] * scale;
        }
    }
    __syncthreads();

    // ---- softmax: 4 threads per row (writes 0 for c>r across all 64 cols) -
    {
        const int r = tid >> 2;            // 0..63
        const int p = tid & 3;             // 16 cols each
        if (r < L) {
            float* row = &S[r * SST];
            const int c0 = p * 16;
            float m = -1e30f;
            #pragma unroll 4
            for (int c = c0; c < c0 + 16; ++c)
                if (c <= r) m = fmaxf(m, row[c]);
            m = fmaxf(m, __shfl_xor_sync(0xffffffffu, m, 1));
            m = fmaxf(m, __shfl_xor_sync(0xffffffffu, m, 2));
            float sum = 0.f;
            #pragma unroll 4
            for (int c = c0; c < c0 + 16; ++c) {
                float e = (c <= r) ? __expf(row[c] - m) : 0.f;
                row[c] = e;
                sum += e;
            }
            sum += __shfl_xor_sync(0xffffffffu, sum, 1);
            sum += __shfl_xor_sync(0xffffffffu, sum, 2);
            float inv = 1.f / sum;
            #pragma unroll 4
            for (int c = c0; c < c0 + 16; ++c) row[c] *= inv;
        }
    }
    __syncthreads();

    // ---- O = P V  (2x10 tile, half2 V) + fp16 hi/lo epilogue --------------
    {
        const int rg = tid >> 3;           // rows rg*2, rg*2+1
        const int dg = tid & 7;            // d pairs dg*5..dg*5+4 (cols dg*10..+9)
        float accO[2][10];
        #pragma unroll
        for (int i = 0; i < 2; ++i)
            #pragma unroll
            for (int u = 0; u < 10; ++u) accO[i][u] = 0.f;
        const int cmax = rg * 2 + 1;
        for (int c = 0; c <= cmax; ++c) {
            float sv0 = S[(rg * 2) * SST + c];
            float sv1 = S[(rg * 2 + 1) * SST + c];
            #pragma unroll
            for (int u = 0; u < 5; ++u) {
                float2 f = __half22float2(Vs2[c * VST + dg * 5 + u]);
                accO[0][2 * u]     += sv0 * f.x;
                accO[0][2 * u + 1] += sv0 * f.y;
                accO[1][2 * u]     += sv1 * f.x;
                accO[1][2 * u + 1] += sv1 * f.y;
            }
        }
        #pragma unroll
        for (int i = 0; i < 2; ++i) {
            int r = rg * 2 + i;
            if (r < L) {
                size_t o = (size_t)(st + r) * D_MODEL + (size_t)h * HD + dg * 10;
                #pragma unroll
                for (int u = 0; u < 10; ++u) {
                    float v = accO[i][u];
                    __half hi = __float2half_rn(v);
                    ah[o + u] = hi;
                    al[o + u] = __float2half_rn(v - __half2float(hi));
                }
            }
        }
    }
}

// ---------------------------------------------------------------------------
// launch
// ---------------------------------------------------------------------------
extern "C" void kernel_launch(void* const* d_in, const int* in_sizes, int n_in,
                              void* d_out, int out_size)
{
    const float* x    = (const float*)d_in[0];
    const float* rope = (const float*)d_in[1];
    const int*   cu   = (const int*)  d_in[2];
    const float* Wqkv = (const float*)d_in[3];
    const float* bqkv = (const float*)d_in[4];
    const float* Wo   = (const float*)d_in[5];
    const float* bo   = (const float*)d_in[6];
    float* out = (float*)d_out;

    const int T = in_sizes[0] / D_MODEL;   // 4096
    const int nseg = in_sizes[2] - 1;      // 64

    float* qkv_p;
    __half *xh, *xl, *wq, *wo, *ah, *al;
    cudaGetSymbolAddress((void**)&qkv_p, g_qkv);
    cudaGetSymbolAddress((void**)&xh, g_xh);
    cudaGetSymbolAddress((void**)&xl, g_xl);
    cudaGetSymbolAddress((void**)&wq, g_wq);
    cudaGetSymbolAddress((void**)&wo, g_wo);
    cudaGetSymbolAddress((void**)&ah, g_ah);
    cudaGetSymbolAddress((void**)&al, g_al);

    const int smem128 = NSTAGE * (2 * 128 * 64 + 128 * 64);   // 98304
    const int smem64  = NSTAGE * (2 * 64 * 64 + 128 * 64);    // 65536
    cudaFuncSetAttribute(gemm_fp16x2<128>,
                         cudaFuncAttributeMaxDynamicSharedMemorySize, smem128);
    cudaFuncSetAttribute(gemm_fp16x2<64>,
                         cudaFuncAttributeMaxDynamicSharedMemorySize, smem64);

    // 0) operand prep
    {
        int n = T * D_MODEL;
        split_f16_kernel<<<(n + 255) / 256, 256>>>(x, xh, xl, n);
        dim3 blk(32, 8);
        transpose_f16_kernel<<<dim3(E3 / 32, KDIM / 32), blk>>>(Wqkv, wq, KDIM, E3);
        transpose_f16_kernel<<<dim3(D_MODEL / 32, KDIM / 32), blk>>>(Wo, wo, KDIM, D_MODEL);
    }

    // 1) QKV projection: [T,1280] x [1280,3840] + bqkv   (BM=128)
    {
        dim3 grid(E3 / GBN, T / 128);
        gemm_fp16x2<128><<<grid, 256, smem128>>>(T, E3, KDIM, xh, xl, wq, bqkv, qkv_p);
    }

    // 2) fused RoPE + windowed attention -> fp16 hi/lo
    {
        int smem = (2 * WIN * QKS + WIN * SST) * (int)sizeof(float)
                 + WIN * VST * (int)sizeof(__half2);          // 68352
        cudaFuncSetAttribute(attn_fused_kernel,
                             cudaFuncAttributeMaxDynamicSharedMemorySize, smem);
        dim3 grid(nseg, NHEAD);
        attn_fused_kernel<<<grid, 256, smem>>>(cu, rope, T, ah, al);
    }

    // 3) output projection: [T,1280] x [1280,1280] + bo   (BM=64, 640 CTAs)
    {
        dim3 grid(D_MODEL / GBN, T / 64);
        gemm_fp16x2<64><<<grid, 256, smem64>>>(T, D_MODEL, KDIM, ah, al, wo, bo, out);
    }
}

// round 12
// speedup vs baseline: 1.2995x; 1.2995x over previous
#include <cuda_runtime.h>
#include <cuda_bf16.h>
#include <cuda_fp16.h>
#include <math.h>
#include <stdint.h>

// Problem constants (fixed by setup_inputs)
#define T_MAX 4096
#define D_MODEL 1280
#define NHEAD 16
#define HD 80
#define E3 (3 * D_MODEL)   // 3840
#define WIN 64
#define KDIM 1280

// ---------------------------------------------------------------------------
// Scratch (device globals; no allocations allowed)
// ---------------------------------------------------------------------------
__device__ float g_qkv[T_MAX * E3];

__device__ __half g_xh[T_MAX * D_MODEL];      // x split hi/lo (fp16)
__device__ __half g_xl[T_MAX * D_MODEL];
__device__ __half g_wq[E3 * D_MODEL];         // Wqkv^T [N,K] fp16
__device__ __half g_wo[D_MODEL * D_MODEL];    // Wo^T [N,K] fp16
__device__ __half g_ah[T_MAX * D_MODEL];      // attn out split hi/lo (fp16)
__device__ __half g_al[T_MAX * D_MODEL];

// ---------------------------------------------------------------------------
// Low-level helpers (baseline PTX, safe for compute_100)
// ---------------------------------------------------------------------------
__device__ __forceinline__ uint32_t smem_u32(const void* p) {
    uint32_t a;
    asm("{ .reg .u64 t; cvta.to.shared.u64 t, %1; cvt.u32.u64 %0, t; }"
        : "=r"(a) : "l"(p));
    return a;
}

__device__ __forceinline__ void cp_async16(uint32_t dst, const void* src) {
    asm volatile("cp.async.cg.shared.global [%0], [%1], 16;" :: "r"(dst), "l"(src));
}

__device__ __forceinline__ void ldm_x4(uint32_t* r, uint32_t addr) {
    asm volatile("ldmatrix.sync.aligned.m8n8.x4.shared.b16 {%0,%1,%2,%3}, [%4];"
                 : "=r"(r[0]), "=r"(r[1]), "=r"(r[2]), "=r"(r[3]) : "r"(addr));
}

__device__ __forceinline__ void mma_fp16(float* d, const uint32_t* a, const uint32_t* b) {
    asm volatile(
        "mma.sync.aligned.m16n8k16.row.col.f32.f16.f16.f32 "
        "{%0,%1,%2,%3}, {%4,%5,%6,%7}, {%8,%9}, {%0,%1,%2,%3};"
        : "+f"(d[0]), "+f"(d[1]), "+f"(d[2]), "+f"(d[3])
        : "r"(a[0]), "r"(a[1]), "r"(a[2]), "r"(a[3]), "r"(b[0]), "r"(b[1]));
}

// ---------------------------------------------------------------------------
// GEMM: C[M,N] = (Ah+Al)[M,K] @ B[N,K]^T + bias[N]  (fp32 accum, fp16 ops)
// 2 products: Ah*B + Al*B.  128x128 tile, BK=32, 4-stage cp.async pipeline,
// 1 sync/chunk, XOR-swizzled 64B rows. 2 CTAs/SM (96 KB smem, 126 regs).
// (R9 configuration — proven 475us total.)
// ---------------------------------------------------------------------------
#define GBM 128
#define GBN 128
#define GBK 32
#define TILE_B (128 * 64)              // 8192 bytes per sub-tile (64B rows)
#define STAGE_B (3 * TILE_B)           // Ah, Al, B = 24576 bytes
#define NSTAGE 4

__device__ __forceinline__ uint32_t sw_off(int row, int ch) {
    return (uint32_t)(row * 64) + ((uint32_t)(ch ^ ((row >> 1) & 3)) << 4);
}

__global__ void __launch_bounds__(256, 2)
gemm_fp16x2(int M, int N, int K,
            const __half* __restrict__ Ah, const __half* __restrict__ Al,
            const __half* __restrict__ B,
            const float* __restrict__ bias, float* __restrict__ C)
{
    extern __shared__ __align__(128) char dsm[];
    const uint32_t sbase = smem_u32(dsm);

    const int tid  = threadIdx.x;
    const int wid  = tid >> 5;
    const int lane = tid & 31;
    const int warp_m = wid >> 2;       // 0..1
    const int warp_n = wid & 3;        // 0..3
    const int m0 = blockIdx.y * GBM;
    const int n0 = blockIdx.x * GBN;

    const int NC = K / GBK;            // 40

    auto load_stage = [&](int cidx) {
        const uint32_t sb = sbase + (uint32_t)(cidx % NSTAGE) * STAGE_B;
        const int k0 = cidx * GBK;
        const __half* srcs[3] = {
            Ah + (size_t)m0 * K + k0,
            Al + (size_t)m0 * K + k0,
            B  + (size_t)n0 * K + k0
        };
        #pragma unroll
        for (int t = 0; t < 3; ++t) {
            const __half* sp = srcs[t];
            #pragma unroll
            for (int j = 0; j < 2; ++j) {
                int e   = tid + j * 256;       // 0..511
                int row = e >> 2;              // 0..127
                int ch  = e & 3;               // 16B chunk in 64B row
                cp_async16(sb + (uint32_t)t * TILE_B + sw_off(row, ch),
                           sp + (size_t)row * K + ch * 8);
            }
        }
        asm volatile("cp.async.commit_group;");
    };

    float acc[4][4][4];
    #pragma unroll
    for (int i = 0; i < 4; ++i)
        #pragma unroll
        for (int j = 0; j < 4; ++j)
            #pragma unroll
            for (int q = 0; q < 4; ++q) acc[i][j][q] = 0.f;

    load_stage(0);
    load_stage(1);
    load_stage(2);

    const int a_row = lane & 15;
    const int a_kch = (lane >> 4);
    const int b_row = (lane & 7) + ((lane >> 4) << 3);
    const int b_kch = ((lane >> 3) & 1);

    for (int c = 0; c < NC; ++c) {
        if (c + 2 < NC) {
            asm volatile("cp.async.wait_group 2;");
        } else if (c + 1 < NC) {
            asm volatile("cp.async.wait_group 1;");
        } else {
            asm volatile("cp.async.wait_group 0;");
        }
        __syncthreads();
        if (c + 3 < NC) load_stage(c + 3);     // overlaps compute below

        const uint32_t sb = sbase + (uint32_t)(c % NSTAGE) * STAGE_B;

        #pragma unroll
        for (int kk = 0; kk < 2; ++kk) {
            const int kc = kk * 2;
            uint32_t aH[4][4], bF[2][4];
            #pragma unroll
            for (int ma = 0; ma < 4; ++ma) {
                int row = warp_m * 64 + ma * 16 + a_row;
                ldm_x4(aH[ma], sb + 0 * TILE_B + sw_off(row, kc + a_kch));
            }
            #pragma unroll
            for (int np = 0; np < 2; ++np) {
                int row = warp_n * 32 + np * 16 + b_row;
                ldm_x4(bF[np], sb + 2 * TILE_B + sw_off(row, kc + b_kch));
            }
            #pragma unroll
            for (int ma = 0; ma < 4; ++ma)
                #pragma unroll
                for (int nb = 0; nb < 4; ++nb)
                    mma_fp16(acc[ma][nb], aH[ma], &bF[nb >> 1][(nb & 1) * 2]);
            uint32_t aL[4][4];
            #pragma unroll
            for (int ma = 0; ma < 4; ++ma) {
                int row = warp_m * 64 + ma * 16 + a_row;
                ldm_x4(aL[ma], sb + 1 * TILE_B + sw_off(row, kc + a_kch));
            }
            #pragma unroll
            for (int ma = 0; ma < 4; ++ma)
                #pragma unroll
                for (int nb = 0; nb < 4; ++nb)
                    mma_fp16(acc[ma][nb], aL[ma], &bF[nb >> 1][(nb & 1) * 2]);
        }
    }

    const int er = lane >> 2;
    const int ec = (lane & 3) * 2;
    #pragma unroll
    for (int ma = 0; ma < 4; ++ma) {
        int gr = m0 + warp_m * 64 + ma * 16 + er;
        #pragma unroll
        for (int nb = 0; nb < 4; ++nb) {
            int gc = n0 + warp_n * 32 + nb * 8 + ec;
            float b0 = __ldg(&bias[gc]);
            float b1 = __ldg(&bias[gc + 1]);
            float2 v0 = make_float2(acc[ma][nb][0] + b0, acc[ma][nb][1] + b1);
            float2 v1 = make_float2(acc[ma][nb][2] + b0, acc[ma][nb][3] + b1);
            *(float2*)&C[(size_t)gr * N + gc] = v0;
            *(float2*)&C[(size_t)(gr + 8) * N + gc] = v1;
        }
    }
}

// ---------------------------------------------------------------------------
// Split fp32 -> fp16 hi/lo
// ---------------------------------------------------------------------------
__global__ void split_f16_kernel(const float* __restrict__ x,
                                 __half* __restrict__ h,
                                 __half* __restrict__ l, int n)
{
    int i = blockIdx.x * blockDim.x + threadIdx.x;
    if (i < n) {
        float v = x[i];
        __half hi = __float2half_rn(v);
        h[i] = hi;
        l[i] = __float2half_rn(v - __half2float(hi));
    }
}

// ---------------------------------------------------------------------------
// Transpose + convert both weights in ONE launch:
//   z==0: Wqkv [1280,3840] -> g_wq [3840,1280]
//   z==1: Wo   [1280,1280] -> g_wo [1280,1280]
// ---------------------------------------------------------------------------
__global__ void transpose_both_kernel(const float* __restrict__ Wqkv,
                                      const float* __restrict__ Wo,
                                      __half* __restrict__ twq,
                                      __half* __restrict__ two)
{
    __shared__ float tile[32][33];
    const int z = blockIdx.z;
    const float* W = z ? Wo : Wqkv;
    __half* t = z ? two : twq;
    const int Nd = z ? D_MODEL : E3;
    const int Kd = KDIM;
    int kb = blockIdx.y * 32, nb = blockIdx.x * 32;
    if (nb >= Nd) return;
    int tx = threadIdx.x, ty = threadIdx.y;    // 32 x 8
    #pragma unroll
    for (int i = 0; i < 32; i += 8)
        tile[ty + i][tx] = W[(size_t)(kb + ty + i) * Nd + nb + tx];
    __syncthreads();
    #pragma unroll
    for (int i = 0; i < 32; i += 8)
        t[(size_t)(nb + ty + i) * Kd + kb + tx] = __float2half_rn(tile[tx][ty + i]);
}

// ---------------------------------------------------------------------------
// Fused RoPE + windowed causal attention + fp16 split epilogue.
// 256 threads per (segment, head). Fully-unrolled register-tiled matmuls
// (R9 S-phase) + half2 V tile (R10's verified-safe piece).
// ---------------------------------------------------------------------------
#define QKS 81
#define SST 65
#define VST 40   // half2 stride for V tile

__global__ void __launch_bounds__(256, 2)
attn_fused_kernel(const int* __restrict__ cu, const float* __restrict__ rope,
                  int T,
                  __half* __restrict__ ah, __half* __restrict__ al)
{
    extern __shared__ float sm[];
    float*   Qs  = sm;                        // [64][81]
    float*   Ks  = Qs + WIN * QKS;            // [64][81]
    __half2* Vs2 = (__half2*)(Ks + WIN * QKS);// [64][40] half2
    float*   S   = (float*)(Vs2 + WIN * VST); // [64][65]

    const int seg = blockIdx.x;
    const int h   = blockIdx.y;
    const int st  = cu[seg];
    int L = cu[seg + 1] - st;
    if (L > WIN) L = WIN;
    const int tid = threadIdx.x;
    const float scale = 0.11180339887498948f;   // 1/sqrt(80)

    // ---- load + RoPE ------------------------------------------------------
    for (int e = tid; e < WIN * 40; e += 256) {
        int r = e / 40, j = e % 40;
        float q0 = 0.f, q1 = 0.f, k0 = 0.f, k1 = 0.f;
        if (r < L) {
            size_t base = (size_t)(st + r) * E3 + (size_t)h * HD;
            float ang = rope[(st + r) * 40 + j];
            float c = cosf(ang), s = sinf(ang);
            float qr = g_qkv[base + j],           qi = g_qkv[base + 40 + j];
            float kr = g_qkv[base + D_MODEL + j], ki = g_qkv[base + D_MODEL + 40 + j];
            q0 = qr * c - qi * s;  q1 = qr * s + qi * c;
            k0 = kr * c - ki * s;  k1 = kr * s + ki * c;
        }
        Qs[r * QKS + j]      = q0;
        Qs[r * QKS + 40 + j] = q1;
        Ks[r * QKS + j]      = k0;
        Ks[r * QKS + 40 + j] = k1;
    }
    // V -> half2 tile (d pairs contiguous)
    for (int e = tid; e < WIN * VST; e += 256) {
        int r = e / VST, dp = e % VST;
        float2 v = make_float2(0.f, 0.f);
        if (r < L) {
            const float* p = &g_qkv[(size_t)(st + r) * E3 + (size_t)h * HD
                                    + 2 * D_MODEL + 2 * dp];
            v.x = p[0]; v.y = p[1];
        }
        Vs2[r * VST + dp] = __floats2half2_rn(v.x, v.y);
    }
    __syncthreads();

    // ---- S = Q K^T * scale  (2x8 register tile, fully unrolled — R9) ------
    {
        const int rg = tid >> 3;           // 0..31 -> rows rg*2, rg*2+1
        const int cg = tid & 7;            // cols cg + 8*j
        float accS[2][8];
        #pragma unroll
        for (int i = 0; i < 2; ++i)
            #pragma unroll
            for (int j = 0; j < 8; ++j) accS[i][j] = 0.f;
        for (int d = 0; d < HD; ++d) {
            float qv[2], kv[8];
            #pragma unroll
            for (int i = 0; i < 2; ++i) qv[i] = Qs[(rg * 2 + i) * QKS + d];
            #pragma unroll
            for (int j = 0; j < 8; ++j) kv[j] = Ks[(cg + 8 * j) * QKS + d];
            #pragma unroll
            for (int i = 0; i < 2; ++i)
                #pragma unroll
                for (int j = 0; j < 8; ++j)
                    accS[i][j] += qv[i] * kv[j];
        }
        #pragma unroll
        for (int i = 0; i < 2; ++i)
            #pragma unroll
            for (int j = 0; j < 8; ++j)
                S[(rg * 2 + i) * SST + cg + 8 * j] = accS[i][j] * scale;
    }
    __syncthreads();

    // ---- softmax: 4 threads per row ---------------------------------------
    {
        const int r = tid >> 2;            // 0..63
        const int p = tid & 3;             // 16 cols each
        if (r < L) {
            float* row = &S[r * SST];
            const int c0 = p * 16;
            float m = -1e30f;
            #pragma unroll 4
            for (int c = c0; c < c0 + 16; ++c)
                if (c <= r) m = fmaxf(m, row[c]);
            m = fmaxf(m, __shfl_xor_sync(0xffffffffu, m, 1));
            m = fmaxf(m, __shfl_xor_sync(0xffffffffu, m, 2));
            float sum = 0.f;
            #pragma unroll 4
            for (int c = c0; c < c0 + 16; ++c) {
                float e = (c <= r) ? __expf(row[c] - m) : 0.f;
                row[c] = e;
                sum += e;
            }
            sum += __shfl_xor_sync(0xffffffffu, sum, 1);
            sum += __shfl_xor_sync(0xffffffffu, sum, 2);
            float inv = 1.f / sum;
            #pragma unroll 4
            for (int c = c0; c < c0 + 16; ++c) row[c] *= inv;
        }
    }
    __syncthreads();

    // ---- O = P V  (2x10 tile, half2 V, causal outer bound) + fp16 split ---
    {
        const int rg = tid >> 3;           // rows rg*2, rg*2+1
        const int dg = tid & 7;            // d pairs dg*5..dg*5+4
        float accO[2][10];
        #pragma unroll
        for (int i = 0; i < 2; ++i)
            #pragma unroll
            for (int u = 0; u < 10; ++u) accO[i][u] = 0.f;
        const int cmax = rg * 2 + 1;       // causal outer bound (R9-style)
        for (int c = 0; c <= cmax; ++c) {
            float sv0 = S[(rg * 2) * SST + c];
            float sv1 = S[(rg * 2 + 1) * SST + c];
            #pragma unroll
            for (int u = 0; u < 5; ++u) {
                float2 f = __half22float2(Vs2[c * VST + dg * 5 + u]);
                accO[0][2 * u]     += sv0 * f.x;
                accO[0][2 * u + 1] += sv0 * f.y;
                accO[1][2 * u]     += sv1 * f.x;
                accO[1][2 * u + 1] += sv1 * f.y;
            }
        }
        #pragma unroll
        for (int i = 0; i < 2; ++i) {
            int r = rg * 2 + i;
            if (r < L) {
                size_t o = (size_t)(st + r) * D_MODEL + (size_t)h * HD + dg * 10;
                #pragma unroll
                for (int u = 0; u < 10; ++u) {
                    float v = accO[i][u];
                    __half hi = __float2half_rn(v);
                    ah[o + u] = hi;
                    al[o + u] = __float2half_rn(v - __half2float(hi));
                }
            }
        }
    }
}

// ---------------------------------------------------------------------------
// launch
// ---------------------------------------------------------------------------
extern "C" void kernel_launch(void* const* d_in, const int* in_sizes, int n_in,
                              void* d_out, int out_size)
{
    const float* x    = (const float*)d_in[0];
    const float* rope = (const float*)d_in[1];
    const int*   cu   = (const int*)  d_in[2];
    const float* Wqkv = (const float*)d_in[3];
    const float* bqkv = (const float*)d_in[4];
    const float* Wo   = (const float*)d_in[5];
    const float* bo   = (const float*)d_in[6];
    float* out = (float*)d_out;

    const int T = in_sizes[0] / D_MODEL;   // 4096
    const int nseg = in_sizes[2] - 1;      // 64

    float* qkv_p;
    __half *xh, *xl, *wq, *wo, *ah, *al;
    cudaGetSymbolAddress((void**)&qkv_p, g_qkv);
    cudaGetSymbolAddress((void**)&xh, g_xh);
    cudaGetSymbolAddress((void**)&xl, g_xl);
    cudaGetSymbolAddress((void**)&wq, g_wq);
    cudaGetSymbolAddress((void**)&wo, g_wo);
    cudaGetSymbolAddress((void**)&ah, g_ah);
    cudaGetSymbolAddress((void**)&al, g_al);

    const int gemm_smem = NSTAGE * STAGE_B;   // 98304
    cudaFuncSetAttribute(gemm_fp16x2,
                         cudaFuncAttributeMaxDynamicSharedMemorySize, gemm_smem);

    // 0) operand prep
    {
        int n = T * D_MODEL;
        split_f16_kernel<<<(n + 255) / 256, 256>>>(x, xh, xl, n);
        dim3 blk(32, 8);
        transpose_both_kernel<<<dim3(E3 / 32, KDIM / 32, 2), blk>>>(Wqkv, Wo, wq, wo);
    }

    // 1) QKV projection: [T,1280] x [1280,3840] + bqkv
    {
        dim3 grid(E3 / GBN, T / GBM);
        gemm_fp16x2<<<grid, 256, gemm_smem>>>(T, E3, KDIM, xh, xl, wq, bqkv, qkv_p);
    }

    // 2) fused RoPE + windowed attention -> fp16 hi/lo
    {
        int smem = (2 * WIN * QKS + WIN * SST) * (int)sizeof(float)
                 + WIN * VST * (int)sizeof(__half2);          // 68352
        cudaFuncSetAttribute(attn_fused_kernel,
                             cudaFuncAttributeMaxDynamicSharedMemorySize, smem);
        dim3 grid(nseg, NHEAD);
        attn_fused_kernel<<<grid, 256, smem>>>(cu, rope, T, ah, al);
    }

    // 3) output projection: [T,1280] x [1280,1280] + bo
    {
        dim3 grid(D_MODEL / GBN, T / GBM);
        gemm_fp16x2<<<grid, 256, gemm_smem>>>(T, D_MODEL, KDIM, ah, al, wo, bo, out);
    }
}

// round 13
// speedup vs baseline: 1.3178x; 1.0141x over previous
#include <cuda_runtime.h>
#include <cuda_bf16.h>
#include <cuda_fp16.h>
#include <math.h>
#include <stdint.h>

// Problem constants (fixed by setup_inputs)
#define T_MAX 4096
#define D_MODEL 1280
#define NHEAD 16
#define HD 80
#define E3 (3 * D_MODEL)   // 3840
#define WIN 64
#define KDIM 1280

// ---------------------------------------------------------------------------
// Scratch (device globals; no allocations allowed)
// ---------------------------------------------------------------------------
__device__ float g_qkv[T_MAX * E3];

__device__ __half g_xh[T_MAX * D_MODEL];      // x split hi/lo (fp16)
__device__ __half g_xl[T_MAX * D_MODEL];
__device__ __half g_wq[E3 * D_MODEL];         // Wqkv^T [N,K] fp16
__device__ __half g_wo[D_MODEL * D_MODEL];    // Wo^T [N,K] fp16
__device__ __half g_ah[T_MAX * D_MODEL];      // attn out split hi/lo (fp16)
__device__ __half g_al[T_MAX * D_MODEL];

// ---------------------------------------------------------------------------
// Low-level helpers (baseline PTX, safe for compute_100)
// ---------------------------------------------------------------------------
__device__ __forceinline__ uint32_t smem_u32(const void* p) {
    uint32_t a;
    asm("{ .reg .u64 t; cvta.to.shared.u64 t, %1; cvt.u32.u64 %0, t; }"
        : "=r"(a) : "l"(p));
    return a;
}

__device__ __forceinline__ void cp_async16(uint32_t dst, const void* src) {
    asm volatile("cp.async.cg.shared.global [%0], [%1], 16;" :: "r"(dst), "l"(src));
}

__device__ __forceinline__ void ldm_x4(uint32_t* r, uint32_t addr) {
    asm volatile("ldmatrix.sync.aligned.m8n8.x4.shared.b16 {%0,%1,%2,%3}, [%4];"
                 : "=r"(r[0]), "=r"(r[1]), "=r"(r[2]), "=r"(r[3]) : "r"(addr));
}

__device__ __forceinline__ void mma_fp16(float* d, const uint32_t* a, const uint32_t* b) {
    asm volatile(
        "mma.sync.aligned.m16n8k16.row.col.f32.f16.f16.f32 "
        "{%0,%1,%2,%3}, {%4,%5,%6,%7}, {%8,%9}, {%0,%1,%2,%3};"
        : "+f"(d[0]), "+f"(d[1]), "+f"(d[2]), "+f"(d[3])
        : "r"(a[0]), "r"(a[1]), "r"(a[2]), "r"(a[3]), "r"(b[0]), "r"(b[1]));
}

// ---------------------------------------------------------------------------
// GEMM: C[M,N] = (Ah+Al)[M,K] @ B[N,K]^T + bias[N]  (fp32 accum, fp16 ops)
// 2 products: Ah*B + Al*B.  128x128 tile, BK=32, 4-stage cp.async pipeline,
// 1 sync/chunk, XOR-swizzled 64B rows. 2 CTAs/SM (96 KB smem, 126 regs).
// ---------------------------------------------------------------------------
#define GBM 128
#define GBN 128
#define GBK 32
#define TILE_B (128 * 64)              // 8192 bytes per sub-tile (64B rows)
#define STAGE_B (3 * TILE_B)           // Ah, Al, B = 24576 bytes
#define NSTAGE 4

__device__ __forceinline__ uint32_t sw_off(int row, int ch) {
    return (uint32_t)(row * 64) + ((uint32_t)(ch ^ ((row >> 1) & 3)) << 4);
}

__global__ void __launch_bounds__(256, 2)
gemm_fp16x2(int M, int N, int K,
            const __half* __restrict__ Ah, const __half* __restrict__ Al,
            const __half* __restrict__ B,
            const float* __restrict__ bias, float* __restrict__ C)
{
    extern __shared__ __align__(128) char dsm[];
    const uint32_t sbase = smem_u32(dsm);

    const int tid  = threadIdx.x;
    const int wid  = tid >> 5;
    const int lane = tid & 31;
    const int warp_m = wid >> 2;       // 0..1
    const int warp_n = wid & 3;        // 0..3
    const int m0 = blockIdx.y * GBM;
    const int n0 = blockIdx.x * GBN;

    const int NC = K / GBK;            // 40

    auto load_stage = [&](int cidx) {
        const uint32_t sb = sbase + (uint32_t)(cidx % NSTAGE) * STAGE_B;
        const int k0 = cidx * GBK;
        const __half* srcs[3] = {
            Ah + (size_t)m0 * K + k0,
            Al + (size_t)m0 * K + k0,
            B  + (size_t)n0 * K + k0
        };
        #pragma unroll
        for (int t = 0; t < 3; ++t) {
            const __half* sp = srcs[t];
            #pragma unroll
            for (int j = 0; j < 2; ++j) {
                int e   = tid + j * 256;       // 0..511
                int row = e >> 2;              // 0..127
                int ch  = e & 3;               // 16B chunk in 64B row
                cp_async16(sb + (uint32_t)t * TILE_B + sw_off(row, ch),
                           sp + (size_t)row * K + ch * 8);
            }
        }
        asm volatile("cp.async.commit_group;");
    };

    float acc[4][4][4];
    #pragma unroll
    for (int i = 0; i < 4; ++i)
        #pragma unroll
        for (int j = 0; j < 4; ++j)
            #pragma unroll
            for (int q = 0; q < 4; ++q) acc[i][j][q] = 0.f;

    load_stage(0);
    load_stage(1);
    load_stage(2);

    const int a_row = lane & 15;
    const int a_kch = (lane >> 4);
    const int b_row = (lane & 7) + ((lane >> 4) << 3);
    const int b_kch = ((lane >> 3) & 1);

    for (int c = 0; c < NC; ++c) {
        if (c + 2 < NC) {
            asm volatile("cp.async.wait_group 2;");
        } else if (c + 1 < NC) {
            asm volatile("cp.async.wait_group 1;");
        } else {
            asm volatile("cp.async.wait_group 0;");
        }
        __syncthreads();
        if (c + 3 < NC) load_stage(c + 3);     // overlaps compute below

        const uint32_t sb = sbase + (uint32_t)(c % NSTAGE) * STAGE_B;

        #pragma unroll
        for (int kk = 0; kk < 2; ++kk) {
            const int kc = kk * 2;
            uint32_t aH[4][4], bF[2][4];
            #pragma unroll
            for (int ma = 0; ma < 4; ++ma) {
                int row = warp_m * 64 + ma * 16 + a_row;
                ldm_x4(aH[ma], sb + 0 * TILE_B + sw_off(row, kc + a_kch));
            }
            #pragma unroll
            for (int np = 0; np < 2; ++np) {
                int row = warp_n * 32 + np * 16 + b_row;
                ldm_x4(bF[np], sb + 2 * TILE_B + sw_off(row, kc + b_kch));
            }
            #pragma unroll
            for (int ma = 0; ma < 4; ++ma)
                #pragma unroll
                for (int nb = 0; nb < 4; ++nb)
                    mma_fp16(acc[ma][nb], aH[ma], &bF[nb >> 1][(nb & 1) * 2]);
            uint32_t aL[4][4];
            #pragma unroll
            for (int ma = 0; ma < 4; ++ma) {
                int row = warp_m * 64 + ma * 16 + a_row;
                ldm_x4(aL[ma], sb + 1 * TILE_B + sw_off(row, kc + a_kch));
            }
            #pragma unroll
            for (int ma = 0; ma < 4; ++ma)
                #pragma unroll
                for (int nb = 0; nb < 4; ++nb)
                    mma_fp16(acc[ma][nb], aL[ma], &bF[nb >> 1][(nb & 1) * 2]);
        }
    }

    const int er = lane >> 2;
    const int ec = (lane & 3) * 2;
    #pragma unroll
    for (int ma = 0; ma < 4; ++ma) {
        int gr = m0 + warp_m * 64 + ma * 16 + er;
        #pragma unroll
        for (int nb = 0; nb < 4; ++nb) {
            int gc = n0 + warp_n * 32 + nb * 8 + ec;
            float b0 = __ldg(&bias[gc]);
            float b1 = __ldg(&bias[gc + 1]);
            float2 v0 = make_float2(acc[ma][nb][0] + b0, acc[ma][nb][1] + b1);
            float2 v1 = make_float2(acc[ma][nb][2] + b0, acc[ma][nb][3] + b1);
            *(float2*)&C[(size_t)gr * N + gc] = v0;
            *(float2*)&C[(size_t)(gr + 8) * N + gc] = v1;
        }
    }
}

// ---------------------------------------------------------------------------
// Split fp32 -> fp16 hi/lo (vectorized: float4 in, half2 out)
// ---------------------------------------------------------------------------
__global__ void split_f16_kernel(const float4* __restrict__ x4,
                                 __half2* __restrict__ h2,
                                 __half2* __restrict__ l2, int n4)
{
    int i = blockIdx.x * blockDim.x + threadIdx.x;
    if (i < n4) {
        float4 v = x4[i];
        __half2 hi01 = __floats2half2_rn(v.x, v.y);
        __half2 hi23 = __floats2half2_rn(v.z, v.w);
        float2 f01 = __half22float2(hi01);
        float2 f23 = __half22float2(hi23);
        h2[2 * i]     = hi01;
        h2[2 * i + 1] = hi23;
        l2[2 * i]     = __floats2half2_rn(v.x - f01.x, v.y - f01.y);
        l2[2 * i + 1] = __floats2half2_rn(v.z - f23.x, v.w - f23.y);
    }
}

// ---------------------------------------------------------------------------
// Transpose + convert both weights in ONE launch:
//   z==0: Wqkv [1280,3840] -> g_wq [3840,1280]
//   z==1: Wo   [1280,1280] -> g_wo [1280,1280]
// ---------------------------------------------------------------------------
__global__ void transpose_both_kernel(const float* __restrict__ Wqkv,
                                      const float* __restrict__ Wo,
                                      __half* __restrict__ twq,
                                      __half* __restrict__ two)
{
    __shared__ float tile[32][33];
    const int z = blockIdx.z;
    const float* W = z ? Wo : Wqkv;
    __half* t = z ? two : twq;
    const int Nd = z ? D_MODEL : E3;
    const int Kd = KDIM;
    int kb = blockIdx.y * 32, nb = blockIdx.x * 32;
    if (nb >= Nd) return;
    int tx = threadIdx.x, ty = threadIdx.y;    // 32 x 8
    #pragma unroll
    for (int i = 0; i < 32; i += 8)
        tile[ty + i][tx] = W[(size_t)(kb + ty + i) * Nd + nb + tx];
    __syncthreads();
    #pragma unroll
    for (int i = 0; i < 32; i += 8)
        t[(size_t)(nb + ty + i) * Kd + kb + tx] = __float2half_rn(tile[tx][ty + i]);
}

// ---------------------------------------------------------------------------
// Fused RoPE + windowed causal attention + fp16 split epilogue.
// 256 threads per (segment, head), 3 CTAs/SM (smem 68352 x3 = 200 KB/SM).
// ---------------------------------------------------------------------------
#define QKS 81
#define SST 65
#define VST 40   // half2 stride for V tile

__global__ void __launch_bounds__(256, 3)
attn_fused_kernel(const int* __restrict__ cu, const float* __restrict__ rope,
                  int T,
                  __half* __restrict__ ah, __half* __restrict__ al)
{
    extern __shared__ float sm[];
    float*   Qs  = sm;                        // [64][81]
    float*   Ks  = Qs + WIN * QKS;            // [64][81]
    __half2* Vs2 = (__half2*)(Ks + WIN * QKS);// [64][40] half2
    float*   S   = (float*)(Vs2 + WIN * VST); // [64][65]

    const int seg = blockIdx.x;
    const int h   = blockIdx.y;
    const int st  = cu[seg];
    int L = cu[seg + 1] - st;
    if (L > WIN) L = WIN;
    const int tid = threadIdx.x;
    const float scale = 0.11180339887498948f;   // 1/sqrt(80)

    // ---- load + RoPE ------------------------------------------------------
    for (int e = tid; e < WIN * 40; e += 256) {
        int r = e / 40, j = e % 40;
        float q0 = 0.f, q1 = 0.f, k0 = 0.f, k1 = 0.f;
        if (r < L) {
            size_t base = (size_t)(st + r) * E3 + (size_t)h * HD;
            float ang = rope[(st + r) * 40 + j];
            float c = cosf(ang), s = sinf(ang);
            float qr = g_qkv[base + j],           qi = g_qkv[base + 40 + j];
            float kr = g_qkv[base + D_MODEL + j], ki = g_qkv[base + D_MODEL + 40 + j];
            q0 = qr * c - qi * s;  q1 = qr * s + qi * c;
            k0 = kr * c - ki * s;  k1 = kr * s + ki * c;
        }
        Qs[r * QKS + j]      = q0;
        Qs[r * QKS + 40 + j] = q1;
        Ks[r * QKS + j]      = k0;
        Ks[r * QKS + 40 + j] = k1;
    }
    // V -> half2 tile (d pairs contiguous)
    for (int e = tid; e < WIN * VST; e += 256) {
        int r = e / VST, dp = e % VST;
        float2 v = make_float2(0.f, 0.f);
        if (r < L) {
            const float* p = &g_qkv[(size_t)(st + r) * E3 + (size_t)h * HD
                                    + 2 * D_MODEL + 2 * dp];
            v.x = p[0]; v.y = p[1];
        }
        Vs2[r * VST + dp] = __floats2half2_rn(v.x, v.y);
    }
    __syncthreads();

    // ---- S = Q K^T * scale  (2x8 register tile, fully unrolled) -----------
    {
        const int rg = tid >> 3;           // 0..31 -> rows rg*2, rg*2+1
        const int cg = tid & 7;            // cols cg + 8*j
        float accS[2][8];
        #pragma unroll
        for (int i = 0; i < 2; ++i)
            #pragma unroll
            for (int j = 0; j < 8; ++j) accS[i][j] = 0.f;
        for (int d = 0; d < HD; ++d) {
            float qv[2], kv[8];
            #pragma unroll
            for (int i = 0; i < 2; ++i) qv[i] = Qs[(rg * 2 + i) * QKS + d];
            #pragma unroll
            for (int j = 0; j < 8; ++j) kv[j] = Ks[(cg + 8 * j) * QKS + d];
            #pragma unroll
            for (int i = 0; i < 2; ++i)
                #pragma unroll
                for (int j = 0; j < 8; ++j)
                    accS[i][j] += qv[i] * kv[j];
        }
        #pragma unroll
        for (int i = 0; i < 2; ++i)
            #pragma unroll
            for (int j = 0; j < 8; ++j)
                S[(rg * 2 + i) * SST + cg + 8 * j] = accS[i][j] * scale;
    }
    __syncthreads();

    // ---- softmax: 4 threads per row ---------------------------------------
    {
        const int r = tid >> 2;            // 0..63
        const int p = tid & 3;             // 16 cols each
        if (r < L) {
            float* row = &S[r * SST];
            const int c0 = p * 16;
            float m = -1e30f;
            #pragma unroll 4
            for (int c = c0; c < c0 + 16; ++c)
                if (c <= r) m = fmaxf(m, row[c]);
            m = fmaxf(m, __shfl_xor_sync(0xffffffffu, m, 1));
            m = fmaxf(m, __shfl_xor_sync(0xffffffffu, m, 2));
            float sum = 0.f;
            #pragma unroll 4
            for (int c = c0; c < c0 + 16; ++c) {
                float e = (c <= r) ? __expf(row[c] - m) : 0.f;
                row[c] = e;
                sum += e;
            }
            sum += __shfl_xor_sync(0xffffffffu, sum, 1);
            sum += __shfl_xor_sync(0xffffffffu, sum, 2);
            float inv = 1.f / sum;
            #pragma unroll 4
            for (int c = c0; c < c0 + 16; ++c) row[c] *= inv;
        }
    }
    __syncthreads();

    // ---- O = P V  (2x10 tile, half2 V, causal outer bound) + fp16 split ---
    {
        const int rg = tid >> 3;           // rows rg*2, rg*2+1
        const int dg = tid & 7;            // d pairs dg*5..dg*5+4
        float accO[2][10];
        #pragma unroll
        for (int i = 0; i < 2; ++i)
            #pragma unroll
            for (int u = 0; u < 10; ++u) accO[i][u] = 0.f;
        const int cmax = rg * 2 + 1;       // causal outer bound
        for (int c = 0; c <= cmax; ++c) {
            float sv0 = S[(rg * 2) * SST + c];
            float sv1 = S[(rg * 2 + 1) * SST + c];
            #pragma unroll
            for (int u = 0; u < 5; ++u) {
                float2 f = __half22float2(Vs2[c * VST + dg * 5 + u]);
                accO[0][2 * u]     += sv0 * f.x;
                accO[0][2 * u + 1] += sv0 * f.y;
                accO[1][2 * u]     += sv1 * f.x;
                accO[1][2 * u + 1] += sv1 * f.y;
            }
        }
        #pragma unroll
        for (int i = 0; i < 2; ++i) {
            int r = rg * 2 + i;
            if (r < L) {
                size_t o = (size_t)(st + r) * D_MODEL + (size_t)h * HD + dg * 10;
                #pragma unroll
                for (int u = 0; u < 10; ++u) {
                    float v = accO[i][u];
                    __half hi = __float2half_rn(v);
                    ah[o + u] = hi;
                    al[o + u] = __float2half_rn(v - __half2float(hi));
                }
            }
        }
    }
}

// ---------------------------------------------------------------------------
// launch
// ---------------------------------------------------------------------------
extern "C" void kernel_launch(void* const* d_in, const int* in_sizes, int n_in,
                              void* d_out, int out_size)
{
    const float* x    = (const float*)d_in[0];
    const float* rope = (const float*)d_in[1];
    const int*   cu   = (const int*)  d_in[2];
    const float* Wqkv = (const float*)d_in[3];
    const float* bqkv = (const float*)d_in[4];
    const float* Wo   = (const float*)d_in[5];
    const float* bo   = (const float*)d_in[6];
    float* out = (float*)d_out;

    const int T = in_sizes[0] / D_MODEL;   // 4096
    const int nseg = in_sizes[2] - 1;      // 64

    float* qkv_p;
    __half *xh, *xl, *wq, *wo, *ah, *al;
    cudaGetSymbolAddress((void**)&qkv_p, g_qkv);
    cudaGetSymbolAddress((void**)&xh, g_xh);
    cudaGetSymbolAddress((void**)&xl, g_xl);
    cudaGetSymbolAddress((void**)&wq, g_wq);
    cudaGetSymbolAddress((void**)&wo, g_wo);
    cudaGetSymbolAddress((void**)&ah, g_ah);
    cudaGetSymbolAddress((void**)&al, g_al);

    const int gemm_smem = NSTAGE * STAGE_B;   // 98304
    cudaFuncSetAttribute(gemm_fp16x2,
                         cudaFuncAttributeMaxDynamicSharedMemorySize, gemm_smem);

    // 0) operand prep
    {
        int n4 = (T * D_MODEL) / 4;
        split_f16_kernel<<<(n4 + 255) / 256, 256>>>(
            (const float4*)x, (__half2*)xh, (__half2*)xl, n4);
        dim3 blk(32, 8);
        transpose_both_kernel<<<dim3(E3 / 32, KDIM / 32, 2), blk>>>(Wqkv, Wo, wq, wo);
    }

    // 1) QKV projection: [T,1280] x [1280,3840] + bqkv
    {
        dim3 grid(E3 / GBN, T / GBM);
        gemm_fp16x2<<<grid, 256, gemm_smem>>>(T, E3, KDIM, xh, xl, wq, bqkv, qkv_p);
    }

    // 2) fused RoPE + windowed attention -> fp16 hi/lo
    {
        int smem = (2 * WIN * QKS + WIN * SST) * (int)sizeof(float)
                 + WIN * VST * (int)sizeof(__half2);          // 68352
        cudaFuncSetAttribute(attn_fused_kernel,
                             cudaFuncAttributeMaxDynamicSharedMemorySize, smem);
        dim3 grid(nseg, NHEAD);
        attn_fused_kernel<<<grid, 256, smem>>>(cu, rope, T, ah, al);
    }

    // 3) output projection: [T,1280] x [1280,1280] + bo
    {
        dim3 grid(D_MODEL / GBN, T / GBM);
        gemm_fp16x2<<<grid, 256, gemm_smem>>>(T, D_MODEL, KDIM, ah, al, wo, bo, out);
    }
}

// round 14
// speedup vs baseline: 1.3755x; 1.0438x over previous
#include <cuda_runtime.h>
#include <cuda_bf16.h>
#include <cuda_fp16.h>
#include <math.h>
#include <stdint.h>

// Problem constants (fixed by setup_inputs)
#define T_MAX 4096
#define D_MODEL 1280
#define NHEAD 16
#define HD 80
#define E3 (3 * D_MODEL)   // 3840
#define WIN 64
#define KDIM 1280

// ---------------------------------------------------------------------------
// Scratch (device globals; no allocations allowed)
// ---------------------------------------------------------------------------
__device__ float g_qkv[T_MAX * E3];

__device__ __half g_xh[T_MAX * D_MODEL];      // x split hi/lo (fp16)
__device__ __half g_xl[T_MAX * D_MODEL];
__device__ __half g_wq[E3 * D_MODEL];         // Wqkv^T [N,K] fp16
__device__ __half g_wo[D_MODEL * D_MODEL];    // Wo^T [N,K] fp16
__device__ __half g_ah[T_MAX * D_MODEL];      // attn out split hi/lo (fp16)
__device__ __half g_al[T_MAX * D_MODEL];

// ---------------------------------------------------------------------------
// Low-level helpers (baseline PTX, safe for compute_100)
// ---------------------------------------------------------------------------
__device__ __forceinline__ uint32_t smem_u32(const void* p) {
    uint32_t a;
    asm("{ .reg .u64 t; cvta.to.shared.u64 t, %1; cvt.u32.u64 %0, t; }"
        : "=r"(a) : "l"(p));
    return a;
}

__device__ __forceinline__ void cp_async16(uint32_t dst, const void* src) {
    asm volatile("cp.async.cg.shared.global [%0], [%1], 16;" :: "r"(dst), "l"(src));
}

__device__ __forceinline__ void ldm_x4(uint32_t* r, uint32_t addr) {
    asm volatile("ldmatrix.sync.aligned.m8n8.x4.shared.b16 {%0,%1,%2,%3}, [%4];"
                 : "=r"(r[0]), "=r"(r[1]), "=r"(r[2]), "=r"(r[3]) : "r"(addr));
}

__device__ __forceinline__ void mma_fp16(float* d, const uint32_t* a, const uint32_t* b) {
    asm volatile(
        "mma.sync.aligned.m16n8k16.row.col.f32.f16.f16.f32 "
        "{%0,%1,%2,%3}, {%4,%5,%6,%7}, {%8,%9}, {%0,%1,%2,%3};"
        : "+f"(d[0]), "+f"(d[1]), "+f"(d[2]), "+f"(d[3])
        : "r"(a[0]), "r"(a[1]), "r"(a[2]), "r"(a[3]), "r"(b[0]), "r"(b[1]));
}

// ---------------------------------------------------------------------------
// GEMM: C[M,N] = (Ah+Al)[M,K] @ B[N,K]^T + bias[N]  (fp32 accum, fp16 ops)
// 2 products: Ah*B + Al*B.  128x128 tile, BK=32, 4-stage cp.async pipeline,
// 1 sync/chunk, XOR-swizzled 64B rows. 2 CTAs/SM (96 KB smem, 126 regs).
// ---------------------------------------------------------------------------
#define GBM 128
#define GBN 128
#define GBK 32
#define TILE_B (128 * 64)              // 8192 bytes per sub-tile (64B rows)
#define STAGE_B (3 * TILE_B)           // Ah, Al, B = 24576 bytes
#define NSTAGE 4

__device__ __forceinline__ uint32_t sw_off(int row, int ch) {
    return (uint32_t)(row * 64) + ((uint32_t)(ch ^ ((row >> 1) & 3)) << 4);
}

__global__ void __launch_bounds__(256, 2)
gemm_fp16x2(int M, int N, int K,
            const __half* __restrict__ Ah, const __half* __restrict__ Al,
            const __half* __restrict__ B,
            const float* __restrict__ bias, float* __restrict__ C)
{
    extern __shared__ __align__(128) char dsm[];
    const uint32_t sbase = smem_u32(dsm);

    const int tid  = threadIdx.x;
    const int wid  = tid >> 5;
    const int lane = tid & 31;
    const int warp_m = wid >> 2;       // 0..1
    const int warp_n = wid & 3;        // 0..3
    const int m0 = blockIdx.y * GBM;
    const int n0 = blockIdx.x * GBN;

    const int NC = K / GBK;            // 40

    auto load_stage = [&](int cidx) {
        const uint32_t sb = sbase + (uint32_t)(cidx % NSTAGE) * STAGE_B;
        const int k0 = cidx * GBK;
        const __half* srcs[3] = {
            Ah + (size_t)m0 * K + k0,
            Al + (size_t)m0 * K + k0,
            B  + (size_t)n0 * K + k0
        };
        #pragma unroll
        for (int t = 0; t < 3; ++t) {
            const __half* sp = srcs[t];
            #pragma unroll
            for (int j = 0; j < 2; ++j) {
                int e   = tid + j * 256;       // 0..511
                int row = e >> 2;              // 0..127
                int ch  = e & 3;               // 16B chunk in 64B row
                cp_async16(sb + (uint32_t)t * TILE_B + sw_off(row, ch),
                           sp + (size_t)row * K + ch * 8);
            }
        }
        asm volatile("cp.async.commit_group;");
    };

    float acc[4][4][4];
    #pragma unroll
    for (int i = 0; i < 4; ++i)
        #pragma unroll
        for (int j = 0; j < 4; ++j)
            #pragma unroll
            for (int q = 0; q < 4; ++q) acc[i][j][q] = 0.f;

    load_stage(0);
    load_stage(1);
    load_stage(2);

    const int a_row = lane & 15;
    const int a_kch = (lane >> 4);
    const int b_row = (lane & 7) + ((lane >> 4) << 3);
    const int b_kch = ((lane >> 3) & 1);

    for (int c = 0; c < NC; ++c) {
        if (c + 2 < NC) {
            asm volatile("cp.async.wait_group 2;");
        } else if (c + 1 < NC) {
            asm volatile("cp.async.wait_group 1;");
        } else {
            asm volatile("cp.async.wait_group 0;");
        }
        __syncthreads();
        if (c + 3 < NC) load_stage(c + 3);     // overlaps compute below

        const uint32_t sb = sbase + (uint32_t)(c % NSTAGE) * STAGE_B;

        #pragma unroll
        for (int kk = 0; kk < 2; ++kk) {
            const int kc = kk * 2;
            uint32_t aH[4][4], bF[2][4];
            #pragma unroll
            for (int ma = 0; ma < 4; ++ma) {
                int row = warp_m * 64 + ma * 16 + a_row;
                ldm_x4(aH[ma], sb + 0 * TILE_B + sw_off(row, kc + a_kch));
            }
            #pragma unroll
            for (int np = 0; np < 2; ++np) {
                int row = warp_n * 32 + np * 16 + b_row;
                ldm_x4(bF[np], sb + 2 * TILE_B + sw_off(row, kc + b_kch));
            }
            #pragma unroll
            for (int ma = 0; ma < 4; ++ma)
                #pragma unroll
                for (int nb = 0; nb < 4; ++nb)
                    mma_fp16(acc[ma][nb], aH[ma], &bF[nb >> 1][(nb & 1) * 2]);
            uint32_t aL[4][4];
            #pragma unroll
            for (int ma = 0; ma < 4; ++ma) {
                int row = warp_m * 64 + ma * 16 + a_row;
                ldm_x4(aL[ma], sb + 1 * TILE_B + sw_off(row, kc + a_kch));
            }
            #pragma unroll
            for (int ma = 0; ma < 4; ++ma)
                #pragma unroll
                for (int nb = 0; nb < 4; ++nb)
                    mma_fp16(acc[ma][nb], aL[ma], &bF[nb >> 1][(nb & 1) * 2]);
        }
    }

    const int er = lane >> 2;
    const int ec = (lane & 3) * 2;
    #pragma unroll
    for (int ma = 0; ma < 4; ++ma) {
        int gr = m0 + warp_m * 64 + ma * 16 + er;
        #pragma unroll
        for (int nb = 0; nb < 4; ++nb) {
            int gc = n0 + warp_n * 32 + nb * 8 + ec;
            float b0 = __ldg(&bias[gc]);
            float b1 = __ldg(&bias[gc + 1]);
            float2 v0 = make_float2(acc[ma][nb][0] + b0, acc[ma][nb][1] + b1);
            float2 v1 = make_float2(acc[ma][nb][2] + b0, acc[ma][nb][3] + b1);
            *(float2*)&C[(size_t)gr * N + gc] = v0;
            *(float2*)&C[(size_t)(gr + 8) * N + gc] = v1;
        }
    }
}

// ---------------------------------------------------------------------------
// Split fp32 -> fp16 hi/lo (vectorized: float4 in, half2 out)
// ---------------------------------------------------------------------------
__global__ void split_f16_kernel(const float4* __restrict__ x4,
                                 __half2* __restrict__ h2,
                                 __half2* __restrict__ l2, int n4)
{
    int i = blockIdx.x * blockDim.x + threadIdx.x;
    if (i < n4) {
        float4 v = x4[i];
        __half2 hi01 = __floats2half2_rn(v.x, v.y);
        __half2 hi23 = __floats2half2_rn(v.z, v.w);
        float2 f01 = __half22float2(hi01);
        float2 f23 = __half22float2(hi23);
        h2[2 * i]     = hi01;
        h2[2 * i + 1] = hi23;
        l2[2 * i]     = __floats2half2_rn(v.x - f01.x, v.y - f01.y);
        l2[2 * i + 1] = __floats2half2_rn(v.z - f23.x, v.w - f23.y);
    }
}

// ---------------------------------------------------------------------------
// Transpose + convert both weights in ONE launch:
//   z==0: Wqkv [1280,3840] -> g_wq [3840,1280]
//   z==1: Wo   [1280,1280] -> g_wo [1280,1280]
// ---------------------------------------------------------------------------
__global__ void transpose_both_kernel(const float* __restrict__ Wqkv,
                                      const float* __restrict__ Wo,
                                      __half* __restrict__ twq,
                                      __half* __restrict__ two)
{
    __shared__ float tile[32][33];
    const int z = blockIdx.z;
    const float* W = z ? Wo : Wqkv;
    __half* t = z ? two : twq;
    const int Nd = z ? D_MODEL : E3;
    const int Kd = KDIM;
    int kb = blockIdx.y * 32, nb = blockIdx.x * 32;
    if (nb >= Nd) return;
    int tx = threadIdx.x, ty = threadIdx.y;    // 32 x 8
    #pragma unroll
    for (int i = 0; i < 32; i += 8)
        tile[ty + i][tx] = W[(size_t)(kb + ty + i) * Nd + nb + tx];
    __syncthreads();
    #pragma unroll
    for (int i = 0; i < 32; i += 8)
        t[(size_t)(nb + ty + i) * Kd + kb + tx] = __float2half_rn(tile[tx][ty + i]);
}

// ---------------------------------------------------------------------------
// Fused RoPE + windowed causal attention + fp16 split epilogue.
// 256 threads per (segment, head). Q/K tiles in half2 (stride 41 half2,
// conflict-free) -> smem 47.9 KB -> 4 CTAs/SM.
// ---------------------------------------------------------------------------
#define QKS2 41  // half2 stride for Q/K tiles
#define SST 65
#define VST 40   // half2 stride for V tile

__global__ void __launch_bounds__(256, 4)
attn_fused_kernel(const int* __restrict__ cu, const float* __restrict__ rope,
                  int T,
                  __half* __restrict__ ah, __half* __restrict__ al)
{
    extern __shared__ float sm[];
    __half2* Qs2 = (__half2*)sm;              // [64][41] half2
    __half2* Ks2 = Qs2 + WIN * QKS2;          // [64][41] half2
    __half2* Vs2 = Ks2 + WIN * QKS2;          // [64][40] half2
    float*   S   = (float*)(Vs2 + WIN * VST); // [64][65]

    const int seg = blockIdx.x;
    const int h   = blockIdx.y;
    const int st  = cu[seg];
    int L = cu[seg + 1] - st;
    if (L > WIN) L = WIN;
    const int tid = threadIdx.x;
    const float scale = 0.11180339887498948f;   // 1/sqrt(80)

    // ---- load + RoPE (pairwise: d = 2jp, 2jp+1; partners at +40) ----------
    for (int e = tid; e < WIN * 20; e += 256) {
        int r = e / 20, jp = e % 20;
        float2 qlo = make_float2(0.f, 0.f), qhi = qlo, klo = qlo, khi = qlo;
        if (r < L) {
            size_t base = (size_t)(st + r) * E3 + (size_t)h * HD;
            float2 ang = *(const float2*)&rope[(st + r) * 40 + 2 * jp];
            float c0 = cosf(ang.x), s0 = sinf(ang.x);
            float c1 = cosf(ang.y), s1 = sinf(ang.y);
            float2 qa = *(const float2*)&g_qkv[base + 2 * jp];
            float2 qb = *(const float2*)&g_qkv[base + 40 + 2 * jp];
            float2 ka = *(const float2*)&g_qkv[base + D_MODEL + 2 * jp];
            float2 kb = *(const float2*)&g_qkv[base + D_MODEL + 40 + 2 * jp];
            qlo = make_float2(qa.x * c0 - qb.x * s0, qa.y * c1 - qb.y * s1);
            qhi = make_float2(qa.x * s0 + qb.x * c0, qa.y * s1 + qb.y * c1);
            klo = make_float2(ka.x * c0 - kb.x * s0, ka.y * c1 - kb.y * s1);
            khi = make_float2(ka.x * s0 + kb.x * c0, ka.y * s1 + kb.y * c1);
        }
        Qs2[r * QKS2 + jp]      = __floats2half2_rn(qlo.x, qlo.y);
        Qs2[r * QKS2 + 20 + jp] = __floats2half2_rn(qhi.x, qhi.y);
        Ks2[r * QKS2 + jp]      = __floats2half2_rn(klo.x, klo.y);
        Ks2[r * QKS2 + 20 + jp] = __floats2half2_rn(khi.x, khi.y);
    }
    // V -> half2 tile (d pairs contiguous)
    for (int e = tid; e < WIN * VST; e += 256) {
        int r = e / VST, dp = e % VST;
        float2 v = make_float2(0.f, 0.f);
        if (r < L) {
            const float* p = &g_qkv[(size_t)(st + r) * E3 + (size_t)h * HD
                                    + 2 * D_MODEL + 2 * dp];
            v.x = p[0]; v.y = p[1];
        }
        Vs2[r * VST + dp] = __floats2half2_rn(v.x, v.y);
    }
    __syncthreads();

    // ---- S = Q K^T * scale  (2x8 register tile, half2 operands) -----------
    {
        const int rg = tid >> 3;           // 0..31 -> rows rg*2, rg*2+1
        const int cg = tid & 7;            // cols cg + 8*j
        float accS[2][8];
        #pragma unroll
        for (int i = 0; i < 2; ++i)
            #pragma unroll
            for (int j = 0; j < 8; ++j) accS[i][j] = 0.f;
        for (int dp = 0; dp < 40; ++dp) {
            float2 qv[2], kv[8];
            #pragma unroll
            for (int i = 0; i < 2; ++i)
                qv[i] = __half22float2(Qs2[(rg * 2 + i) * QKS2 + dp]);
            #pragma unroll
            for (int j = 0; j < 8; ++j)
                kv[j] = __half22float2(Ks2[(cg + 8 * j) * QKS2 + dp]);
            #pragma unroll
            for (int i = 0; i < 2; ++i)
                #pragma unroll
                for (int j = 0; j < 8; ++j)
                    accS[i][j] += qv[i].x * kv[j].x + qv[i].y * kv[j].y;
        }
        #pragma unroll
        for (int i = 0; i < 2; ++i)
            #pragma unroll
            for (int j = 0; j < 8; ++j)
                S[(rg * 2 + i) * SST + cg + 8 * j] = accS[i][j] * scale;
    }
    __syncthreads();

    // ---- softmax: 4 threads per row ---------------------------------------
    {
        const int r = tid >> 2;            // 0..63
        const int p = tid & 3;             // 16 cols each
        if (r < L) {
            float* row = &S[r * SST];
            const int c0 = p * 16;
            float m = -1e30f;
            #pragma unroll 4
            for (int c = c0; c < c0 + 16; ++c)
                if (c <= r) m = fmaxf(m, row[c]);
            m = fmaxf(m, __shfl_xor_sync(0xffffffffu, m, 1));
            m = fmaxf(m, __shfl_xor_sync(0xffffffffu, m, 2));
            float sum = 0.f;
            #pragma unroll 4
            for (int c = c0; c < c0 + 16; ++c) {
                float e = (c <= r) ? __expf(row[c] - m) : 0.f;
                row[c] = e;
                sum += e;
            }
            sum += __shfl_xor_sync(0xffffffffu, sum, 1);
            sum += __shfl_xor_sync(0xffffffffu, sum, 2);
            float inv = 1.f / sum;
            #pragma unroll 4
            for (int c = c0; c < c0 + 16; ++c) row[c] *= inv;
        }
    }
    __syncthreads();

    // ---- O = P V  (2x10 tile, half2 V, causal outer bound) + fp16 split ---
    {
        const int rg = tid >> 3;           // rows rg*2, rg*2+1
        const int dg = tid & 7;            // d pairs dg*5..dg*5+4
        float accO[2][10];
        #pragma unroll
        for (int i = 0; i < 2; ++i)
            #pragma unroll
            for (int u = 0; u < 10; ++u) accO[i][u] = 0.f;
        const int cmax = rg * 2 + 1;       // causal outer bound
        for (int c = 0; c <= cmax; ++c) {
            float sv0 = S[(rg * 2) * SST + c];
            float sv1 = S[(rg * 2 + 1) * SST + c];
            #pragma unroll
            for (int u = 0; u < 5; ++u) {
                float2 f = __half22float2(Vs2[c * VST + dg * 5 + u]);
                accO[0][2 * u]     += sv0 * f.x;
                accO[0][2 * u + 1] += sv0 * f.y;
                accO[1][2 * u]     += sv1 * f.x;
                accO[1][2 * u + 1] += sv1 * f.y;
            }
        }
        #pragma unroll
        for (int i = 0; i < 2; ++i) {
            int r = rg * 2 + i;
            if (r < L) {
                size_t o = (size_t)(st + r) * D_MODEL + (size_t)h * HD + dg * 10;
                #pragma unroll
                for (int u = 0; u < 10; ++u) {
                    float v = accO[i][u];
                    __half hi = __float2half_rn(v);
                    ah[o + u] = hi;
                    al[o + u] = __float2half_rn(v - __half2float(hi));
                }
            }
        }
    }
}

// ---------------------------------------------------------------------------
// launch
// ---------------------------------------------------------------------------
extern "C" void kernel_launch(void* const* d_in, const int* in_sizes, int n_in,
                              void* d_out, int out_size)
{
    const float* x    = (const float*)d_in[0];
    const float* rope = (const float*)d_in[1];
    const int*   cu   = (const int*)  d_in[2];
    const float* Wqkv = (const float*)d_in[3];
    const float* bqkv = (const float*)d_in[4];
    const float* Wo   = (const float*)d_in[5];
    const float* bo   = (const float*)d_in[6];
    float* out = (float*)d_out;

    const int T = in_sizes[0] / D_MODEL;   // 4096
    const int nseg = in_sizes[2] - 1;      // 64

    float* qkv_p;
    __half *xh, *xl, *wq, *wo, *ah, *al;
    cudaGetSymbolAddress((void**)&qkv_p, g_qkv);
    cudaGetSymbolAddress((void**)&xh, g_xh);
    cudaGetSymbolAddress((void**)&xl, g_xl);
    cudaGetSymbolAddress((void**)&wq, g_wq);
    cudaGetSymbolAddress((void**)&wo, g_wo);
    cudaGetSymbolAddress((void**)&ah, g_ah);
    cudaGetSymbolAddress((void**)&al, g_al);

    const int gemm_smem = NSTAGE * STAGE_B;   // 98304
    cudaFuncSetAttribute(gemm_fp16x2,
                         cudaFuncAttributeMaxDynamicSharedMemorySize, gemm_smem);

    // 0) operand prep
    {
        int n4 = (T * D_MODEL) / 4;
        split_f16_kernel<<<(n4 + 255) / 256, 256>>>(
            (const float4*)x, (__half2*)xh, (__half2*)xl, n4);
        dim3 blk(32, 8);
        transpose_both_kernel<<<dim3(E3 / 32, KDIM / 32, 2), blk>>>(Wqkv, Wo, wq, wo);
    }

    // 1) QKV projection: [T,1280] x [1280,3840] + bqkv
    {
        dim3 grid(E3 / GBN, T / GBM);
        gemm_fp16x2<<<grid, 256, gemm_smem>>>(T, E3, KDIM, xh, xl, wq, bqkv, qkv_p);
    }

    // 2) fused RoPE + windowed attention -> fp16 hi/lo
    {
        int smem = 2 * WIN * QKS2 * (int)sizeof(__half2)
                 + WIN * VST * (int)sizeof(__half2)
                 + WIN * SST * (int)sizeof(float);            // 47872
        cudaFuncSetAttribute(attn_fused_kernel,
                             cudaFuncAttributeMaxDynamicSharedMemorySize, smem);
        dim3 grid(nseg, NHEAD);
        attn_fused_kernel<<<grid, 256, smem>>>(cu, rope, T, ah, al);
    }

    // 3) output projection: [T,1280] x [1280,1280] + bo
    {
        dim3 grid(D_MODEL / GBN, T / GBM);
        gemm_fp16x2<<<grid, 256, gemm_smem>>>(T, D_MODEL, KDIM, ah, al, wo, bo, out);
    }
}

// round 15
// speedup vs baseline: 2.1337x; 1.5512x over previous
#include <cuda_runtime.h>
#include <cuda_bf16.h>
#include <cuda_fp16.h>
#include <math.h>
#include <stdint.h>

// Problem constants (fixed by setup_inputs)
#define T_MAX 4096
#define D_MODEL 1280
#define NHEAD 16
#define HD 80
#define E3 (3 * D_MODEL)   // 3840
#define WIN 64
#define KDIM 1280

// ---------------------------------------------------------------------------
// Scratch (device globals; no allocations allowed)
// ---------------------------------------------------------------------------
__device__ float g_qkv[T_MAX * E3];

__device__ __half g_xh[T_MAX * D_MODEL];      // x fp16
__device__ __half g_wq[E3 * D_MODEL];         // Wqkv^T [N,K] fp16
__device__ __half g_wo[D_MODEL * D_MODEL];    // Wo^T [N,K] fp16
__device__ __half g_ah[T_MAX * D_MODEL];      // attn out fp16

// ---------------------------------------------------------------------------
// Low-level helpers (baseline PTX, safe for compute_100)
// ---------------------------------------------------------------------------
__device__ __forceinline__ uint32_t smem_u32(const void* p) {
    uint32_t a;
    asm("{ .reg .u64 t; cvta.to.shared.u64 t, %1; cvt.u32.u64 %0, t; }"
        : "=r"(a) : "l"(p));
    return a;
}

__device__ __forceinline__ void cp_async16(uint32_t dst, const void* src) {
    asm volatile("cp.async.cg.shared.global [%0], [%1], 16;" :: "r"(dst), "l"(src));
}

__device__ __forceinline__ void ldm_x4(uint32_t* r, uint32_t addr) {
    asm volatile("ldmatrix.sync.aligned.m8n8.x4.shared.b16 {%0,%1,%2,%3}, [%4];"
                 : "=r"(r[0]), "=r"(r[1]), "=r"(r[2]), "=r"(r[3]) : "r"(addr));
}

__device__ __forceinline__ void mma_fp16(float* d, const uint32_t* a, const uint32_t* b) {
    asm volatile(
        "mma.sync.aligned.m16n8k16.row.col.f32.f16.f16.f32 "
        "{%0,%1,%2,%3}, {%4,%5,%6,%7}, {%8,%9}, {%0,%1,%2,%3};"
        : "+f"(d[0]), "+f"(d[1]), "+f"(d[2]), "+f"(d[3])
        : "r"(a[0]), "r"(a[1]), "r"(a[2]), "r"(a[3]), "r"(b[0]), "r"(b[1]));
}

// ---------------------------------------------------------------------------
// GEMM: C[M,N] = A[M,K] @ B[N,K]^T + bias[N]  (fp32 accum, single fp16 product)
// 128x128 tile, BK=32, 4-stage cp.async pipeline, 1 sync/chunk,
// XOR-swizzled 64B rows. Stage = A tile + B tile = 16 KB; 64 KB total.
// ---------------------------------------------------------------------------
#define GBM 128
#define GBN 128
#define GBK 32
#define TILE_B (128 * 64)              // 8192 bytes per sub-tile (64B rows)
#define STAGE_B (2 * TILE_B)           // A, B = 16384 bytes
#define NSTAGE 4

__device__ __forceinline__ uint32_t sw_off(int row, int ch) {
    return (uint32_t)(row * 64) + ((uint32_t)(ch ^ ((row >> 1) & 3)) << 4);
}

__global__ void __launch_bounds__(256, 2)
gemm_fp16x1(int M, int N, int K,
            const __half* __restrict__ A,
            const __half* __restrict__ B,
            const float* __restrict__ bias, float* __restrict__ C)
{
    extern __shared__ __align__(128) char dsm[];
    const uint32_t sbase = smem_u32(dsm);

    const int tid  = threadIdx.x;
    const int wid  = tid >> 5;
    const int lane = tid & 31;
    const int warp_m = wid >> 2;       // 0..1
    const int warp_n = wid & 3;        // 0..3
    const int m0 = blockIdx.y * GBM;
    const int n0 = blockIdx.x * GBN;

    const int NC = K / GBK;            // 40

    auto load_stage = [&](int cidx) {
        const uint32_t sb = sbase + (uint32_t)(cidx % NSTAGE) * STAGE_B;
        const int k0 = cidx * GBK;
        const __half* srcs[2] = {
            A + (size_t)m0 * K + k0,
            B + (size_t)n0 * K + k0
        };
        #pragma unroll
        for (int t = 0; t < 2; ++t) {
            const __half* sp = srcs[t];
            #pragma unroll
            for (int j = 0; j < 2; ++j) {
                int e   = tid + j * 256;       // 0..511
                int row = e >> 2;              // 0..127
                int ch  = e & 3;               // 16B chunk in 64B row
                cp_async16(sb + (uint32_t)t * TILE_B + sw_off(row, ch),
                           sp + (size_t)row * K + ch * 8);
            }
        }
        asm volatile("cp.async.commit_group;");
    };

    float acc[4][4][4];
    #pragma unroll
    for (int i = 0; i < 4; ++i)
        #pragma unroll
        for (int j = 0; j < 4; ++j)
            #pragma unroll
            for (int q = 0; q < 4; ++q) acc[i][j][q] = 0.f;

    load_stage(0);
    load_stage(1);
    load_stage(2);

    const int a_row = lane & 15;
    const int a_kch = (lane >> 4);
    const int b_row = (lane & 7) + ((lane >> 4) << 3);
    const int b_kch = ((lane >> 3) & 1);

    for (int c = 0; c < NC; ++c) {
        if (c + 2 < NC) {
            asm volatile("cp.async.wait_group 2;");
        } else if (c + 1 < NC) {
            asm volatile("cp.async.wait_group 1;");
        } else {
            asm volatile("cp.async.wait_group 0;");
        }
        __syncthreads();
        if (c + 3 < NC) load_stage(c + 3);     // overlaps compute below

        const uint32_t sb = sbase + (uint32_t)(c % NSTAGE) * STAGE_B;

        #pragma unroll
        for (int kk = 0; kk < 2; ++kk) {
            const int kc = kk * 2;
            uint32_t aF[4][4], bF[2][4];
            #pragma unroll
            for (int ma = 0; ma < 4; ++ma) {
                int row = warp_m * 64 + ma * 16 + a_row;
                ldm_x4(aF[ma], sb + 0 * TILE_B + sw_off(row, kc + a_kch));
            }
            #pragma unroll
            for (int np = 0; np < 2; ++np) {
                int row = warp_n * 32 + np * 16 + b_row;
                ldm_x4(bF[np], sb + 1 * TILE_B + sw_off(row, kc + b_kch));
            }
            #pragma unroll
            for (int ma = 0; ma < 4; ++ma)
                #pragma unroll
                for (int nb = 0; nb < 4; ++nb)
                    mma_fp16(acc[ma][nb], aF[ma], &bF[nb >> 1][(nb & 1) * 2]);
        }
    }

    const int er = lane >> 2;
    const int ec = (lane & 3) * 2;
    #pragma unroll
    for (int ma = 0; ma < 4; ++ma) {
        int gr = m0 + warp_m * 64 + ma * 16 + er;
        #pragma unroll
        for (int nb = 0; nb < 4; ++nb) {
            int gc = n0 + warp_n * 32 + nb * 8 + ec;
            float b0 = __ldg(&bias[gc]);
            float b1 = __ldg(&bias[gc + 1]);
            float2 v0 = make_float2(acc[ma][nb][0] + b0, acc[ma][nb][1] + b1);
            float2 v1 = make_float2(acc[ma][nb][2] + b0, acc[ma][nb][3] + b1);
            *(float2*)&C[(size_t)gr * N + gc] = v0;
            *(float2*)&C[(size_t)(gr + 8) * N + gc] = v1;
        }
    }
}

// ---------------------------------------------------------------------------
// Convert fp32 -> fp16 (vectorized: float4 in, half2 out)
// ---------------------------------------------------------------------------
__global__ void conv_f16_kernel(const float4* __restrict__ x4,
                                __half2* __restrict__ h2, int n4)
{
    int i = blockIdx.x * blockDim.x + threadIdx.x;
    if (i < n4) {
        float4 v = x4[i];
        h2[2 * i]     = __floats2half2_rn(v.x, v.y);
        h2[2 * i + 1] = __floats2half2_rn(v.z, v.w);
    }
}

// ---------------------------------------------------------------------------
// Transpose + convert both weights in ONE launch:
//   z==0: Wqkv [1280,3840] -> g_wq [3840,1280]
//   z==1: Wo   [1280,1280] -> g_wo [1280,1280]
// ---------------------------------------------------------------------------
__global__ void transpose_both_kernel(const float* __restrict__ Wqkv,
                                      const float* __restrict__ Wo,
                                      __half* __restrict__ twq,
                                      __half* __restrict__ two)
{
    __shared__ float tile[32][33];
    const int z = blockIdx.z;
    const float* W = z ? Wo : Wqkv;
    __half* t = z ? two : twq;
    const int Nd = z ? D_MODEL : E3;
    const int Kd = KDIM;
    int kb = blockIdx.y * 32, nb = blockIdx.x * 32;
    if (nb >= Nd) return;
    int tx = threadIdx.x, ty = threadIdx.y;    // 32 x 8
    #pragma unroll
    for (int i = 0; i < 32; i += 8)
        tile[ty + i][tx] = W[(size_t)(kb + ty + i) * Nd + nb + tx];
    __syncthreads();
    #pragma unroll
    for (int i = 0; i < 32; i += 8)
        t[(size_t)(nb + ty + i) * Kd + kb + tx] = __float2half_rn(tile[tx][ty + i]);
}

// ---------------------------------------------------------------------------
// Fused RoPE + windowed causal attention -> fp16 out.
// 256 threads per (segment, head). Q/K/V tiles half2, S fp32. 4 CTAs/SM.
// ---------------------------------------------------------------------------
#define QKS2 41  // half2 stride for Q/K tiles
#define SST 65
#define VST 40   // half2 stride for V tile

__global__ void __launch_bounds__(256, 4)
attn_fused_kernel(const int* __restrict__ cu, const float* __restrict__ rope,
                  int T, __half* __restrict__ ah)
{
    extern __shared__ float sm[];
    __half2* Qs2 = (__half2*)sm;              // [64][41] half2
    __half2* Ks2 = Qs2 + WIN * QKS2;          // [64][41] half2
    __half2* Vs2 = Ks2 + WIN * QKS2;          // [64][40] half2
    float*   S   = (float*)(Vs2 + WIN * VST); // [64][65]

    const int seg = blockIdx.x;
    const int h   = blockIdx.y;
    const int st  = cu[seg];
    int L = cu[seg + 1] - st;
    if (L > WIN) L = WIN;
    const int tid = threadIdx.x;
    const float scale = 0.11180339887498948f;   // 1/sqrt(80)

    // ---- load + RoPE (pairwise: d = 2jp, 2jp+1; partners at +40) ----------
    for (int e = tid; e < WIN * 20; e += 256) {
        int r = e / 20, jp = e % 20;
        float2 qlo = make_float2(0.f, 0.f), qhi = qlo, klo = qlo, khi = qlo;
        if (r < L) {
            size_t base = (size_t)(st + r) * E3 + (size_t)h * HD;
            float2 ang = *(const float2*)&rope[(st + r) * 40 + 2 * jp];
            float c0 = cosf(ang.x), s0 = sinf(ang.x);
            float c1 = cosf(ang.y), s1 = sinf(ang.y);
            float2 qa = *(const float2*)&g_qkv[base + 2 * jp];
            float2 qb = *(const float2*)&g_qkv[base + 40 + 2 * jp];
            float2 ka = *(const float2*)&g_qkv[base + D_MODEL + 2 * jp];
            float2 kb = *(const float2*)&g_qkv[base + D_MODEL + 40 + 2 * jp];
            qlo = make_float2(qa.x * c0 - qb.x * s0, qa.y * c1 - qb.y * s1);
            qhi = make_float2(qa.x * s0 + qb.x * c0, qa.y * s1 + qb.y * c1);
            klo = make_float2(ka.x * c0 - kb.x * s0, ka.y * c1 - kb.y * s1);
            khi = make_float2(ka.x * s0 + kb.x * c0, ka.y * s1 + kb.y * c1);
        }
        Qs2[r * QKS2 + jp]      = __floats2half2_rn(qlo.x, qlo.y);
        Qs2[r * QKS2 + 20 + jp] = __floats2half2_rn(qhi.x, qhi.y);
        Ks2[r * QKS2 + jp]      = __floats2half2_rn(klo.x, klo.y);
        Ks2[r * QKS2 + 20 + jp] = __floats2half2_rn(khi.x, khi.y);
    }
    // V -> half2 tile (d pairs contiguous)
    for (int e = tid; e < WIN * VST; e += 256) {
        int r = e / VST, dp = e % VST;
        float2 v = make_float2(0.f, 0.f);
        if (r < L) {
            const float* p = &g_qkv[(size_t)(st + r) * E3 + (size_t)h * HD
                                    + 2 * D_MODEL + 2 * dp];
            v.x = p[0]; v.y = p[1];
        }
        Vs2[r * VST + dp] = __floats2half2_rn(v.x, v.y);
    }
    __syncthreads();

    // ---- S = Q K^T * scale  (2x8 register tile, half2 operands) -----------
    {
        const int rg = tid >> 3;           // 0..31 -> rows rg*2, rg*2+1
        const int cg = tid & 7;            // cols cg + 8*j
        float accS[2][8];
        #pragma unroll
        for (int i = 0; i < 2; ++i)
            #pragma unroll
            for (int j = 0; j < 8; ++j) accS[i][j] = 0.f;
        for (int dp = 0; dp < 40; ++dp) {
            float2 qv[2], kv[8];
            #pragma unroll
            for (int i = 0; i < 2; ++i)
                qv[i] = __half22float2(Qs2[(rg * 2 + i) * QKS2 + dp]);
            #pragma unroll
            for (int j = 0; j < 8; ++j)
                kv[j] = __half22float2(Ks2[(cg + 8 * j) * QKS2 + dp]);
            #pragma unroll
            for (int i = 0; i < 2; ++i)
                #pragma unroll
                for (int j = 0; j < 8; ++j)
                    accS[i][j] += qv[i].x * kv[j].x + qv[i].y * kv[j].y;
        }
        #pragma unroll
        for (int i = 0; i < 2; ++i)
            #pragma unroll
            for (int j = 0; j < 8; ++j)
                S[(rg * 2 + i) * SST + cg + 8 * j] = accS[i][j] * scale;
    }
    __syncthreads();

    // ---- softmax: 4 threads per row ---------------------------------------
    {
        const int r = tid >> 2;            // 0..63
        const int p = tid & 3;             // 16 cols each
        if (r < L) {
            float* row = &S[r * SST];
            const int c0 = p * 16;
            float m = -1e30f;
            #pragma unroll 4
            for (int c = c0; c < c0 + 16; ++c)
                if (c <= r) m = fmaxf(m, row[c]);
            m = fmaxf(m, __shfl_xor_sync(0xffffffffu, m, 1));
            m = fmaxf(m, __shfl_xor_sync(0xffffffffu, m, 2));
            float sum = 0.f;
            #pragma unroll 4
            for (int c = c0; c < c0 + 16; ++c) {
                float e = (c <= r) ? __expf(row[c] - m) : 0.f;
                row[c] = e;
                sum += e;
            }
            sum += __shfl_xor_sync(0xffffffffu, sum, 1);
            sum += __shfl_xor_sync(0xffffffffu, sum, 2);
            float inv = 1.f / sum;
            #pragma unroll 4
            for (int c = c0; c < c0 + 16; ++c) row[c] *= inv;
        }
    }
    __syncthreads();

    // ---- O = P V  (2x10 tile, half2 V, causal outer bound) -> fp16 --------
    {
        const int rg = tid >> 3;           // rows rg*2, rg*2+1
        const int dg = tid & 7;            // d pairs dg*5..dg*5+4
        float accO[2][10];
        #pragma unroll
        for (int i = 0; i < 2; ++i)
            #pragma unroll
            for (int u = 0; u < 10; ++u) accO[i][u] = 0.f;
        const int cmax = rg * 2 + 1;       // causal outer bound
        for (int c = 0; c <= cmax; ++c) {
            float sv0 = S[(rg * 2) * SST + c];
            float sv1 = S[(rg * 2 + 1) * SST + c];
            #pragma unroll
            for (int u = 0; u < 5; ++u) {
                float2 f = __half22float2(Vs2[c * VST + dg * 5 + u]);
                accO[0][2 * u]     += sv0 * f.x;
                accO[0][2 * u + 1] += sv0 * f.y;
                accO[1][2 * u]     += sv1 * f.x;
                accO[1][2 * u + 1] += sv1 * f.y;
            }
        }
        #pragma unroll
        for (int i = 0; i < 2; ++i) {
            int r = rg * 2 + i;
            if (r < L) {
                __half2* o2 = (__half2*)&ah[(size_t)(st + r) * D_MODEL
                                            + (size_t)h * HD + dg * 10];
                #pragma unroll
                for (int u = 0; u < 5; ++u)
                    o2[u] = __floats2half2_rn(accO[i][2 * u], accO[i][2 * u + 1]);
            }
        }
    }
}

// ---------------------------------------------------------------------------
// launch
// ---------------------------------------------------------------------------
extern "C" void kernel_launch(void* const* d_in, const int* in_sizes, int n_in,
                              void* d_out, int out_size)
{
    const float* x    = (const float*)d_in[0];
    const float* rope = (const float*)d_in[1];
    const int*   cu   = (const int*)  d_in[2];
    const float* Wqkv = (const float*)d_in[3];
    const float* bqkv = (const float*)d_in[4];
    const float* Wo   = (const float*)d_in[5];
    const float* bo   = (const float*)d_in[6];
    float* out = (float*)d_out;

    const int T = in_sizes[0] / D_MODEL;   // 4096
    const int nseg = in_sizes[2] - 1;      // 64

    float* qkv_p;
    __half *xh, *wq, *wo, *ah;
    cudaGetSymbolAddress((void**)&qkv_p, g_qkv);
    cudaGetSymbolAddress((void**)&xh, g_xh);
    cudaGetSymbolAddress((void**)&wq, g_wq);
    cudaGetSymbolAddress((void**)&wo, g_wo);
    cudaGetSymbolAddress((void**)&ah, g_ah);

    const int gemm_smem = NSTAGE * STAGE_B;   // 65536
    cudaFuncSetAttribute(gemm_fp16x1,
                         cudaFuncAttributeMaxDynamicSharedMemorySize, gemm_smem);

    // 0) operand prep
    {
        int n4 = (T * D_MODEL) / 4;
        conv_f16_kernel<<<(n4 + 255) / 256, 256>>>(
            (const float4*)x, (__half2*)xh, n4);
        dim3 blk(32, 8);
        transpose_both_kernel<<<dim3(E3 / 32, KDIM / 32, 2), blk>>>(Wqkv, Wo, wq, wo);
    }

    // 1) QKV projection: [T,1280] x [1280,3840] + bqkv
    {
        dim3 grid(E3 / GBN, T / GBM);
        gemm_fp16x1<<<grid, 256, gemm_smem>>>(T, E3, KDIM, xh, wq, bqkv, qkv_p);
    }

    // 2) fused RoPE + windowed attention -> fp16
    {
        int smem = 2 * WIN * QKS2 * (int)sizeof(__half2)
                 + WIN * VST * (int)sizeof(__half2)
                 + WIN * SST * (int)sizeof(float);            // 47872
        cudaFuncSetAttribute(attn_fused_kernel,
                             cudaFuncAttributeMaxDynamicSharedMemorySize, smem);
        dim3 grid(nseg, NHEAD);
        attn_fused_kernel<<<grid, 256, smem>>>(cu, rope, T, ah);
    }

    // 3) output projection: [T,1280] x [1280,1280] + bo
    {
        dim3 grid(D_MODEL / GBN, T / GBM);
        gemm_fp16x1<<<grid, 256, gemm_smem>>>(T, D_MODEL, KDIM, ah, wo, bo, out);
    }
}

// round 17
// speedup vs baseline: 2.1360x; 1.0011x over previous
#include <cuda_runtime.h>
#include <cuda_bf16.h>
#include <cuda_fp16.h>
#include <math.h>
#include <stdint.h>

// Problem constants (fixed by setup_inputs)
#define T_MAX 4096
#define D_MODEL 1280
#define NHEAD 16
#define HD 80
#define E3 (3 * D_MODEL)   // 3840
#define WIN 64
#define KDIM 1280

// ---------------------------------------------------------------------------
// Scratch (device globals; no allocations allowed)
// ---------------------------------------------------------------------------
__device__ __half g_qkvh[T_MAX * E3];         // QKV intermediate, fp16
__device__ __half g_xh[T_MAX * D_MODEL];      // x fp16
__device__ __half g_wq[E3 * D_MODEL];         // Wqkv^T [N,K] fp16
__device__ __half g_wo[D_MODEL * D_MODEL];    // Wo^T [N,K] fp16
__device__ __half g_ah[T_MAX * D_MODEL];      // attn out fp16

// ---------------------------------------------------------------------------
// Low-level helpers (baseline PTX, safe for compute_100)
// ---------------------------------------------------------------------------
__device__ __forceinline__ uint32_t smem_u32(const void* p) {
    uint32_t a;
    asm("{ .reg .u64 t; cvta.to.shared.u64 t, %1; cvt.u32.u64 %0, t; }"
        : "=r"(a) : "l"(p));
    return a;
}

__device__ __forceinline__ void cp_async16(uint32_t dst, const void* src) {
    asm volatile("cp.async.cg.shared.global [%0], [%1], 16;" :: "r"(dst), "l"(src));
}

__device__ __forceinline__ void ldm_x4(uint32_t* r, uint32_t addr) {
    asm volatile("ldmatrix.sync.aligned.m8n8.x4.shared.b16 {%0,%1,%2,%3}, [%4];"
                 : "=r"(r[0]), "=r"(r[1]), "=r"(r[2]), "=r"(r[3]) : "r"(addr));
}

__device__ __forceinline__ void mma_fp16(float* d, const uint32_t* a, const uint32_t* b) {
    asm volatile(
        "mma.sync.aligned.m16n8k16.row.col.f32.f16.f16.f32 "
        "{%0,%1,%2,%3}, {%4,%5,%6,%7}, {%8,%9}, {%0,%1,%2,%3};"
        : "+f"(d[0]), "+f"(d[1]), "+f"(d[2]), "+f"(d[3])
        : "r"(a[0]), "r"(a[1]), "r"(a[2]), "r"(a[3]), "r"(b[0]), "r"(b[1]));
}

// epilogue store: fp32 or fp16 output, 2 consecutive columns
__device__ __forceinline__ void store2(float* C, size_t idx, float a, float b) {
    *(float2*)&C[idx] = make_float2(a, b);
}
__device__ __forceinline__ void store2(__half* C, size_t idx, float a, float b) {
    *(__half2*)&C[idx] = __floats2half2_rn(a, b);
}

// ---------------------------------------------------------------------------
// GEMM: C[M,N] = A[M,K] @ B[N,K]^T + bias[N]  (fp32 accum, fp16 operands)
// 128x128 tile, BK=64 per sync stage (two verified BK=32 sub-stages),
// NSTAGE=3 x 32KB = 96 KB smem, 2 CTAs/SM, 20 syncs total.
// ---------------------------------------------------------------------------
#define GBM 128
#define GBN 128
#define TILE_B (128 * 64)              // 8192 B per sub-tile (64B rows)
#define SUB_B  (2 * TILE_B)            // A+B sub-stage = 16384 B
#define STAGE_B (2 * SUB_B)            // 64-K stage = 32768 B
#define NSTAGE 3

__device__ __forceinline__ uint32_t sw_off(int row, int ch) {
    return (uint32_t)(row * 64) + ((uint32_t)(ch ^ ((row >> 1) & 3)) << 4);
}

template <typename OutT>
__global__ void __launch_bounds__(256, 2)
gemm_fp16x1(int M, int N, int K,
            const __half* __restrict__ A,
            const __half* __restrict__ B,
            const float* __restrict__ bias, OutT* __restrict__ C)
{
    extern __shared__ __align__(128) char dsm[];
    const uint32_t sbase = smem_u32(dsm);

    const int tid  = threadIdx.x;
    const int wid  = tid >> 5;
    const int lane = tid & 31;
    const int warp_m = wid >> 2;       // 0..1
    const int warp_n = wid & 3;        // 0..3
    const int m0 = blockIdx.y * GBM;
    const int n0 = blockIdx.x * GBN;

    const int NC2 = K / 64;            // 20 stages of BK=64

    auto load_stage = [&](int sidx) {
        const uint32_t sb = sbase + (uint32_t)(sidx % NSTAGE) * STAGE_B;
        const int k0 = sidx * 64;
        #pragma unroll
        for (int sub = 0; sub < 2; ++sub) {
            const __half* srcs[2] = {
                A + (size_t)m0 * K + k0 + sub * 32,
                B + (size_t)n0 * K + k0 + sub * 32
            };
            const uint32_t so = sb + (uint32_t)sub * SUB_B;
            #pragma unroll
            for (int t = 0; t < 2; ++t) {
                const __half* sp = srcs[t];
                #pragma unroll
                for (int j = 0; j < 2; ++j) {
                    int e   = tid + j * 256;       // 0..511
                    int row = e >> 2;              // 0..127
                    int ch  = e & 3;               // 16B chunk in 64B row
                    cp_async16(so + (uint32_t)t * TILE_B + sw_off(row, ch),
                               sp + (size_t)row * K + ch * 8);
                }
            }
        }
        asm volatile("cp.async.commit_group;");
    };

    float acc[4][4][4];
    #pragma unroll
    for (int i = 0; i < 4; ++i)
        #pragma unroll
        for (int j = 0; j < 4; ++j)
            #pragma unroll
            for (int q = 0; q < 4; ++q) acc[i][j][q] = 0.f;

    load_stage(0);
    load_stage(1);

    const int a_row = lane & 15;
    const int a_kch = (lane >> 4);
    const int b_row = (lane & 7) + ((lane >> 4) << 3);
    const int b_kch = ((lane >> 3) & 1);

    for (int s = 0; s < NC2; ++s) {
        if (s + 1 < NC2) {
            asm volatile("cp.async.wait_group 1;");
        } else {
            asm volatile("cp.async.wait_group 0;");
        }
        __syncthreads();
        if (s + 2 < NC2) load_stage(s + 2);    // overlaps compute below

        const uint32_t sb = sbase + (uint32_t)(s % NSTAGE) * STAGE_B;

        #pragma unroll
        for (int sub = 0; sub < 2; ++sub) {
            const uint32_t sb2 = sb + (uint32_t)sub * SUB_B;
            #pragma unroll
            for (int kk = 0; kk < 2; ++kk) {
                const int kc = kk * 2;
                uint32_t aF[4][4], bF[2][4];
                #pragma unroll
                for (int ma = 0; ma < 4; ++ma) {
                    int row = warp_m * 64 + ma * 16 + a_row;
                    ldm_x4(aF[ma], sb2 + sw_off(row, kc + a_kch));
                }
                #pragma unroll
                for (int np = 0; np < 2; ++np) {
                    int row = warp_n * 32 + np * 16 + b_row;
                    ldm_x4(bF[np], sb2 + TILE_B + sw_off(row, kc + b_kch));
                }
                #pragma unroll
                for (int ma = 0; ma < 4; ++ma)
                    #pragma unroll
                    for (int nb = 0; nb < 4; ++nb)
                        mma_fp16(acc[ma][nb], aF[ma], &bF[nb >> 1][(nb & 1) * 2]);
            }
        }
        // no trailing sync: next iteration's sync protects buffer reuse
    }

    const int er = lane >> 2;
    const int ec = (lane & 3) * 2;
    #pragma unroll
    for (int ma = 0; ma < 4; ++ma) {
        int gr = m0 + warp_m * 64 + ma * 16 + er;
        #pragma unroll
        for (int nb = 0; nb < 4; ++nb) {
            int gc = n0 + warp_n * 32 + nb * 8 + ec;
            float b0 = __ldg(&bias[gc]);
            float b1 = __ldg(&bias[gc + 1]);
            store2(C, (size_t)gr * N + gc,       acc[ma][nb][0] + b0, acc[ma][nb][1] + b1);
            store2(C, (size_t)(gr + 8) * N + gc, acc[ma][nb][2] + b0, acc[ma][nb][3] + b1);
        }
    }
}

// ---------------------------------------------------------------------------
// Convert fp32 -> fp16 (vectorized: float4 in, half2 out)
// ---------------------------------------------------------------------------
__global__ void conv_f16_kernel(const float4* __restrict__ x4,
                                __half2* __restrict__ h2, int n4)
{
    int i = blockIdx.x * blockDim.x + threadIdx.x;
    if (i < n4) {
        float4 v = x4[i];
        h2[2 * i]     = __floats2half2_rn(v.x, v.y);
        h2[2 * i + 1] = __floats2half2_rn(v.z, v.w);
    }
}

// ---------------------------------------------------------------------------
// Transpose + convert both weights in ONE launch:
//   z==0: Wqkv [1280,3840] -> g_wq [3840,1280]
//   z==1: Wo   [1280,1280] -> g_wo [1280,1280]
// ---------------------------------------------------------------------------
__global__ void transpose_both_kernel(const float* __restrict__ Wqkv,
                                      const float* __restrict__ Wo,
                                      __half* __restrict__ twq,
                                      __half* __restrict__ two)
{
    __shared__ float tile[32][33];
    const int z = blockIdx.z;
    const float* W = z ? Wo : Wqkv;
    __half* t = z ? two : twq;
    const int Nd = z ? D_MODEL : E3;
    const int Kd = KDIM;
    int kb = blockIdx.y * 32, nb = blockIdx.x * 32;
    if (nb >= Nd) return;
    int tx = threadIdx.x, ty = threadIdx.y;    // 32 x 8
    #pragma unroll
    for (int i = 0; i < 32; i += 8)
        tile[ty + i][tx] = W[(size_t)(kb + ty + i) * Nd + nb + tx];
    __syncthreads();
    #pragma unroll
    for (int i = 0; i < 32; i += 8)
        t[(size_t)(nb + ty + i) * Kd + kb + tx] = __float2half_rn(tile[tx][ty + i]);
}

// ---------------------------------------------------------------------------
// Fused RoPE + windowed causal attention -> fp16 out.
// 256 threads per (segment, head). qkv read as half2; Q/K rotated in fp32,
// V copied. Tiles half2, S fp32. 4 CTAs/SM (47.9 KB smem).
// ---------------------------------------------------------------------------
#define QKS2 41  // half2 stride for Q/K tiles
#define SST 65
#define VST 40   // half2 stride for V tile
#define E3H2 (E3 / 2)    // row stride of g_qkvh in half2 units (1920)

__global__ void __launch_bounds__(256, 4)
attn_fused_kernel(const int* __restrict__ cu, const float* __restrict__ rope,
                  int T, __half* __restrict__ ah)
{
    extern __shared__ float sm[];
    __half2* Qs2 = (__half2*)sm;              // [64][41] half2
    __half2* Ks2 = Qs2 + WIN * QKS2;          // [64][41] half2
    __half2* Vs2 = Ks2 + WIN * QKS2;          // [64][40] half2
    float*   S   = (float*)(Vs2 + WIN * VST); // [64][65]

    const int seg = blockIdx.x;
    const int h   = blockIdx.y;
    const int st  = cu[seg];
    int L = cu[seg + 1] - st;
    if (L > WIN) L = WIN;
    const int tid = threadIdx.x;
    const float scale = 0.11180339887498948f;   // 1/sqrt(80)

    const __half2* qkv2 = (const __half2*)g_qkvh;

    // ---- load + RoPE (pairwise: d = 2jp, 2jp+1; partners at +40) ----------
    for (int e = tid; e < WIN * 20; e += 256) {
        int r = e / 20, jp = e % 20;
        float2 qlo = make_float2(0.f, 0.f), qhi = qlo, klo = qlo, khi = qlo;
        if (r < L) {
            size_t base2 = (size_t)(st + r) * E3H2 + (size_t)h * 40;
            float2 ang = *(const float2*)&rope[(st + r) * 40 + 2 * jp];
            float c0 = cosf(ang.x), s0 = sinf(ang.x);
            float c1 = cosf(ang.y), s1 = sinf(ang.y);
            float2 qa = __half22float2(qkv2[base2 + jp]);
            float2 qb = __half22float2(qkv2[base2 + 20 + jp]);
            float2 ka = __half22float2(qkv2[base2 + (D_MODEL / 2) + jp]);
            float2 kb = __half22float2(qkv2[base2 + (D_MODEL / 2) + 20 + jp]);
            qlo = make_float2(qa.x * c0 - qb.x * s0, qa.y * c1 - qb.y * s1);
            qhi = make_float2(qa.x * s0 + qb.x * c0, qa.y * s1 + qb.y * c1);
            klo = make_float2(ka.x * c0 - kb.x * s0, ka.y * c1 - kb.y * s1);
            khi = make_float2(ka.x * s0 + kb.x * c0, ka.y * s1 + kb.y * c1);
        }
        Qs2[r * QKS2 + jp]      = __floats2half2_rn(qlo.x, qlo.y);
        Qs2[r * QKS2 + 20 + jp] = __floats2half2_rn(qhi.x, qhi.y);
        Ks2[r * QKS2 + jp]      = __floats2half2_rn(klo.x, klo.y);
        Ks2[r * QKS2 + 20 + jp] = __floats2half2_rn(khi.x, khi.y);
    }
    // V -> half2 tile (plain copy; already fp16)
    for (int e = tid; e < WIN * VST; e += 256) {
        int r = e / VST, dp = e % VST;
        __half2 v = __floats2half2_rn(0.f, 0.f);
        if (r < L)
            v = qkv2[(size_t)(st + r) * E3H2 + (size_t)h * 40 + D_MODEL + dp];
        Vs2[r * VST + dp] = v;
    }
    __syncthreads();

    // ---- S = Q K^T * scale  (2x8 register tile, half2 operands) -----------
    {
        const int rg = tid >> 3;           // 0..31 -> rows rg*2, rg*2+1
        const int cg = tid & 7;            // cols cg + 8*j
        float accS[2][8];
        #pragma unroll
        for (int i = 0; i < 2; ++i)
            #pragma unroll
            for (int j = 0; j < 8; ++j) accS[i][j] = 0.f;
        for (int dp = 0; dp < 40; ++dp) {
            float2 qv[2], kv[8];
            #pragma unroll
            for (int i = 0; i < 2; ++i)
                qv[i] = __half22float2(Qs2[(rg * 2 + i) * QKS2 + dp]);
            #pragma unroll
            for (int j = 0; j < 8; ++j)
                kv[j] = __half22float2(Ks2[(cg + 8 * j) * QKS2 + dp]);
            #pragma unroll
            for (int i = 0; i < 2; ++i)
                #pragma unroll
                for (int j = 0; j < 8; ++j)
                    accS[i][j] += qv[i].x * kv[j].x + qv[i].y * kv[j].y;
        }
        #pragma unroll
        for (int i = 0; i < 2; ++i)
            #pragma unroll
            for (int j = 0; j < 8; ++j)
                S[(rg * 2 + i) * SST + cg + 8 * j] = accS[i][j] * scale;
    }
    __syncthreads();

    // ---- softmax: 4 threads per row ---------------------------------------
    {
        const int r = tid >> 2;            // 0..63
        const int p = tid & 3;             // 16 cols each
        if (r < L) {
            float* row = &S[r * SST];
            const int c0 = p * 16;
            float m = -1e30f;
            #pragma unroll 4
            for (int c = c0; c < c0 + 16; ++c)
                if (c <= r) m = fmaxf(m, row[c]);
            m = fmaxf(m, __shfl_xor_sync(0xffffffffu, m, 1));
            m = fmaxf(m, __shfl_xor_sync(0xffffffffu, m, 2));
            float sum = 0.f;
            #pragma unroll 4
            for (int c = c0; c < c0 + 16; ++c) {
                float e = (c <= r) ? __expf(row[c] - m) : 0.f;
                row[c] = e;
                sum += e;
            }
            sum += __shfl_xor_sync(0xffffffffu, sum, 1);
            sum += __shfl_xor_sync(0xffffffffu, sum, 2);
            float inv = 1.f / sum;
            #pragma unroll 4
            for (int c = c0; c < c0 + 16; ++c) row[c] *= inv;
        }
    }
    __syncthreads();

    // ---- O = P V  (2x10 tile, half2 V, causal outer bound) -> fp16 --------
    {
        const int rg = tid >> 3;           // rows rg*2, rg*2+1
        const int dg = tid & 7;            // d pairs dg*5..dg*5+4
        float accO[2][10];
        #pragma unroll
        for (int i = 0; i < 2; ++i)
            #pragma unroll
            for (int u = 0; u < 10; ++u) accO[i][u] = 0.f;
        const int cmax = rg * 2 + 1;       // causal outer bound
        for (int c = 0; c <= cmax; ++c) {
            float sv0 = S[(rg * 2) * SST + c];
            float sv1 = S[(rg * 2 + 1) * SST + c];
            #pragma unroll
            for (int u = 0; u < 5; ++u) {
                float2 f = __half22float2(Vs2[c * VST + dg * 5 + u]);
                accO[0][2 * u]     += sv0 * f.x;
                accO[0][2 * u + 1] += sv0 * f.y;
                accO[1][2 * u]     += sv1 * f.x;
                accO[1][2 * u + 1] += sv1 * f.y;
            }
        }
        #pragma unroll
        for (int i = 0; i < 2; ++i) {
            int r = rg * 2 + i;
            if (r < L) {
                __half2* o2 = (__half2*)&ah[(size_t)(st + r) * D_MODEL
                                            + (size_t)h * HD + dg * 10];
                #pragma unroll
                for (int u = 0; u < 5; ++u)
                    o2[u] = __floats2half2_rn(accO[i][2 * u], accO[i][2 * u + 1]);
            }
        }
    }
}

// ---------------------------------------------------------------------------
// launch
// ---------------------------------------------------------------------------
extern "C" void kernel_launch(void* const* d_in, const int* in_sizes, int n_in,
                              void* d_out, int out_size)
{
    const float* x    = (const float*)d_in[0];
    const float* rope = (const float*)d_in[1];
    const int*   cu   = (const int*)  d_in[2];
    const float* Wqkv = (const float*)d_in[3];
    const float* bqkv = (const float*)d_in[4];
    const float* Wo   = (const float*)d_in[5];
    const float* bo   = (const float*)d_in[6];
    float* out = (float*)d_out;

    const int T = in_sizes[0] / D_MODEL;   // 4096
    const int nseg = in_sizes[2] - 1;      // 64

    __half *qkvh, *xh, *wq, *wo, *ah;
    cudaGetSymbolAddress((void**)&qkvh, g_qkvh);
    cudaGetSymbolAddress((void**)&xh, g_xh);
    cudaGetSymbolAddress((void**)&wq, g_wq);
    cudaGetSymbolAddress((void**)&wo, g_wo);
    cudaGetSymbolAddress((void**)&ah, g_ah);

    const int gemm_smem = NSTAGE * STAGE_B;   // 98304
    cudaFuncSetAttribute(gemm_fp16x1<__half>,
                         cudaFuncAttributeMaxDynamicSharedMemorySize, gemm_smem);
    cudaFuncSetAttribute(gemm_fp16x1<float>,
                         cudaFuncAttributeMaxDynamicSharedMemorySize, gemm_smem);

    // 0) operand prep
    {
        int n4 = (T * D_MODEL) / 4;
        conv_f16_kernel<<<(n4 + 255) / 256, 256>>>(
            (const float4*)x, (__half2*)xh, n4);
        dim3 blk(32, 8);
        transpose_both_kernel<<<dim3(E3 / 32, KDIM / 32, 2), blk>>>(Wqkv, Wo, wq, wo);
    }

    // 1) QKV projection: [T,1280] x [1280,3840] + bqkv -> fp16
    {
        dim3 grid(E3 / GBN, T / GBM);
        gemm_fp16x1<__half><<<grid, 256, gemm_smem>>>(T, E3, KDIM, xh, wq, bqkv, qkvh);
    }

    // 2) fused RoPE + windowed attention -> fp16
    {
        int smem = 2 * WIN * QKS2 * (int)sizeof(__half2)
                 + WIN * VST * (int)sizeof(__half2)
                 + WIN * SST * (int)sizeof(float);            // 47872
        cudaFuncSetAttribute(attn_fused_kernel,
                             cudaFuncAttributeMaxDynamicSharedMemorySize, smem);
        dim3 grid(nseg, NHEAD);
        attn_fused_kernel<<<grid, 256, smem>>>(cu, rope, T, ah);
    }

    // 3) output projection: [T,1280] x [1280,1280] + bo -> fp32 d_out
    {
        dim3 grid(D_MODEL / GBN, T / GBM);
        gemm_fp16x1<float><<<grid, 256, gemm_smem>>>(T, D_MODEL, KDIM, ah, wo, bo, out);
    }
}